// round 1
// baseline (speedup 1.0000x reference)
#include <cuda_runtime.h>
#include <cuda_bf16.h>
#include <math.h>

// Problem constants
#define B_    4
#define N_    2048
#define DIM_  1024
#define H_    16
#define DH_   64
#define INNER_ 1024
#define ROWS_ (B_ * N_)   // 8192

// Scratch (device globals — no cudaMalloc allowed)
__device__ float g_q [B_ * N_ * INNER_];      // 32 MB
__device__ float g_kv[B_ * N_ * 2 * INNER_];  // 64 MB
__device__ float g_ao[B_ * N_ * INNER_];      // 32 MB

// ---------------------------------------------------------------------------
// SGEMM: C[M,N] = A[M,K] @ B[K,N] (+ bias).  BM=BN=128, BK=8, 256 thr, 8x8 uT
// M,N multiples of 128, K multiple of 8. Row-major everywhere.
// ---------------------------------------------------------------------------
__global__ __launch_bounds__(256, 2)
void sgemm_k(const float* __restrict__ A, const float* __restrict__ Bm,
             const float* __restrict__ bias, float* __restrict__ C,
             int M, int N, int K)
{
    __shared__ float As[8][128];
    __shared__ float Bs[8][128];

    const int bx = blockIdx.x, by = blockIdx.y;
    const int tid = threadIdx.x;
    const int tr = tid >> 4;      // 0..15
    const int tc = tid & 15;      // 0..15

    const float* Ab = A + (size_t)by * 128 * K;
    const float* Bb = Bm + (size_t)bx * 128;

    const int arow = tid >> 1;            // 0..127
    const int acol = (tid & 1) * 4;       // 0 or 4
    const int brow = tid >> 5;            // 0..7
    const int bcol = (tid & 31) * 4;      // 0..124

    float acc[8][8];
#pragma unroll
    for (int i = 0; i < 8; i++)
#pragma unroll
        for (int j = 0; j < 8; j++) acc[i][j] = 0.f;

    for (int k0 = 0; k0 < K; k0 += 8) {
        float4 a4 = *(const float4*)(Ab + (size_t)arow * K + k0 + acol);
        As[acol + 0][arow] = a4.x;
        As[acol + 1][arow] = a4.y;
        As[acol + 2][arow] = a4.z;
        As[acol + 3][arow] = a4.w;
        float4 b4 = *(const float4*)(Bb + (size_t)(k0 + brow) * N + bcol);
        *(float4*)&Bs[brow][bcol] = b4;
        __syncthreads();

#pragma unroll
        for (int kk = 0; kk < 8; kk++) {
            float ar[8], br[8];
            *(float4*)(ar)     = *(const float4*)&As[kk][tr * 8];
            *(float4*)(ar + 4) = *(const float4*)&As[kk][tr * 8 + 4];
            *(float4*)(br)     = *(const float4*)&Bs[kk][tc * 8];
            *(float4*)(br + 4) = *(const float4*)&Bs[kk][tc * 8 + 4];
#pragma unroll
            for (int i = 0; i < 8; i++)
#pragma unroll
                for (int j = 0; j < 8; j++)
                    acc[i][j] = fmaf(ar[i], br[j], acc[i][j]);
        }
        __syncthreads();
    }

    float* Cb = C + (size_t)(by * 128) * N + bx * 128;
#pragma unroll
    for (int i = 0; i < 8; i++) {
        const int row = tr * 8 + i;
#pragma unroll
        for (int j = 0; j < 8; j += 4) {
            const int col = tc * 8 + j;
            float4 v;
            if (bias) {
                v.x = acc[i][j + 0] + bias[bx * 128 + col + 0];
                v.y = acc[i][j + 1] + bias[bx * 128 + col + 1];
                v.z = acc[i][j + 2] + bias[bx * 128 + col + 2];
                v.w = acc[i][j + 3] + bias[bx * 128 + col + 3];
            } else {
                v.x = acc[i][j + 0]; v.y = acc[i][j + 1];
                v.z = acc[i][j + 2]; v.w = acc[i][j + 3];
            }
            *(float4*)(Cb + (size_t)row * N + col) = v;
        }
    }
}

// ---------------------------------------------------------------------------
// Flash attention (causal), fp32. One CTA = one 64-row query block of one
// (b,h). 256 threads, 4x4 register micro-tiles for QK^T and PV. Online
// softmax. Smem = exactly 48KB static: Qs^T | (K^T then P^T) | V.
// q layout: [B,N,INNER] (head h at column h*64); kv: [B,N,2*INNER] (k then v)
// ---------------------------------------------------------------------------
#define FS 64   // tile stride (floats)

__global__ __launch_bounds__(256, 3)
void flash_attn_k(const float* __restrict__ gq, const float* __restrict__ gkv,
                  float* __restrict__ go)
{
    __shared__ float Qs[DH_ * FS];   // Q^T: Qs[d*FS + r]
    __shared__ float KP[DH_ * FS];   // K^T: [d*FS + c]  then  P^T: [c*FS + r]
    __shared__ float Vs[64   * FS];  // V:   Vs[c*FS + d]

    const int b  = blockIdx.z;
    const int h  = blockIdx.y;
    const int ib = blockIdx.x;
    const int tid = threadIdx.x;
    const int tr = tid >> 4;    // 0..15  (row group: rows tr*4..tr*4+3)
    const int tc = tid & 15;    // 0..15  (col group: cols tc*4..tc*4+3)
    const int n0 = ib * 64;
    const float scale = 0.125f; // 1/sqrt(64)

    // --- load Q block (transpose into Qs) ---
    {
        const int r  = tid >> 2;           // 0..63
        const int d0 = (tid & 3) * 16;     // 0,16,32,48
        const float* qp = gq + ((size_t)(b * N_ + n0 + r)) * INNER_ + h * DH_;
#pragma unroll
        for (int u = 0; u < 4; u++) {
            float4 v = *(const float4*)(qp + d0 + u * 4);
            const int d = d0 + u * 4;
            Qs[(d + 0) * FS + r] = v.x;
            Qs[(d + 1) * FS + r] = v.y;
            Qs[(d + 2) * FS + r] = v.z;
            Qs[(d + 3) * FS + r] = v.w;
        }
    }

    float acc[4][4];
    float m_i[4], l_i[4];
#pragma unroll
    for (int i = 0; i < 4; i++) {
        m_i[i] = -INFINITY; l_i[i] = 0.f;
#pragma unroll
        for (int j = 0; j < 4; j++) acc[i][j] = 0.f;
    }

    for (int jb = 0; jb <= ib; jb++) {
        const int c0 = jb * 64;
        __syncthreads();  // previous PV done (and Q load on first iter)

        // --- load K (transposed) and V for this key block ---
        {
            const int c  = tid >> 2;
            const int d0 = (tid & 3) * 16;
            const float* kp = gkv + ((size_t)(b * N_ + c0 + c)) * (2 * INNER_) + h * DH_;
#pragma unroll
            for (int u = 0; u < 4; u++) {
                float4 kv4 = *(const float4*)(kp + d0 + u * 4);
                const int d = d0 + u * 4;
                KP[(d + 0) * FS + c] = kv4.x;
                KP[(d + 1) * FS + c] = kv4.y;
                KP[(d + 2) * FS + c] = kv4.z;
                KP[(d + 3) * FS + c] = kv4.w;
                float4 vv4 = *(const float4*)(kp + INNER_ + d0 + u * 4);
                *(float4*)(Vs + c * FS + d0 + u * 4) = vv4;
            }
        }
        __syncthreads();

        // --- S = Q K^T (4x4 micro-tile) ---
        float s[4][4];
#pragma unroll
        for (int i = 0; i < 4; i++)
#pragma unroll
            for (int j = 0; j < 4; j++) s[i][j] = 0.f;

#pragma unroll 8
        for (int d = 0; d < DH_; d++) {
            float4 qa = *(const float4*)(Qs + d * FS + tr * 4);
            float4 kb = *(const float4*)(KP + d * FS + tc * 4);
            const float* qa_ = &qa.x;
            const float* kb_ = &kb.x;
#pragma unroll
            for (int i = 0; i < 4; i++)
#pragma unroll
                for (int j = 0; j < 4; j++)
                    s[i][j] = fmaf(qa_[i], kb_[j], s[i][j]);
        }

        // --- scale + causal mask (diagonal block only) ---
#pragma unroll
        for (int i = 0; i < 4; i++)
#pragma unroll
            for (int j = 0; j < 4; j++) {
                float v = s[i][j] * scale;
                if (jb == ib && (tc * 4 + j) > (tr * 4 + i)) v = -INFINITY;
                s[i][j] = v;
            }

        // --- online softmax ---
        float mn[4], fac[4];
#pragma unroll
        for (int i = 0; i < 4; i++) {
            float rm = fmaxf(fmaxf(s[i][0], s[i][1]), fmaxf(s[i][2], s[i][3]));
#pragma unroll
            for (int off = 8; off > 0; off >>= 1)
                rm = fmaxf(rm, __shfl_xor_sync(0xffffffffu, rm, off));
            mn[i]  = fmaxf(m_i[i], rm);
            fac[i] = expf(m_i[i] - mn[i]);   // 0 on first block
        }
#pragma unroll
        for (int i = 0; i < 4; i++) {
            float sum = 0.f;
#pragma unroll
            for (int j = 0; j < 4; j++) {
                s[i][j] = expf(s[i][j] - mn[i]);  // masked -> exp(-inf)=0
                sum += s[i][j];
            }
#pragma unroll
            for (int off = 8; off > 0; off >>= 1)
                sum += __shfl_xor_sync(0xffffffffu, sum, off);
            l_i[i] = l_i[i] * fac[i] + sum;
            m_i[i] = mn[i];
#pragma unroll
            for (int j = 0; j < 4; j++) acc[i][j] *= fac[i];
        }

        // --- write P^T into KP (reuse K buffer) ---
        __syncthreads();  // all K reads done
#pragma unroll
        for (int j = 0; j < 4; j++) {
            float4 p4 = make_float4(s[0][j], s[1][j], s[2][j], s[3][j]);
            *(float4*)(KP + (tc * 4 + j) * FS + tr * 4) = p4;
        }
        __syncthreads();

        // --- O += P V (4x4 micro-tile) ---
#pragma unroll 8
        for (int c = 0; c < 64; c++) {
            float4 pa = *(const float4*)(KP + c * FS + tr * 4);
            float4 vb = *(const float4*)(Vs + c * FS + tc * 4);
            const float* pa_ = &pa.x;
            const float* vb_ = &vb.x;
#pragma unroll
            for (int i = 0; i < 4; i++)
#pragma unroll
                for (int j = 0; j < 4; j++)
                    acc[i][j] = fmaf(pa_[i], vb_[j], acc[i][j]);
        }
    }

    // --- epilogue: normalize and store ---
#pragma unroll
    for (int i = 0; i < 4; i++) {
        const float inv = 1.f / l_i[i];
        const int row = n0 + tr * 4 + i;
        float4 o = make_float4(acc[i][0] * inv, acc[i][1] * inv,
                               acc[i][2] * inv, acc[i][3] * inv);
        *(float4*)(go + ((size_t)(b * N_ + row)) * INNER_ + h * DH_ + tc * 4) = o;
    }
}

// ---------------------------------------------------------------------------
extern "C" void kernel_launch(void* const* d_in, const int* in_sizes, int n_in,
                              void* d_out, int out_size)
{
    const float* x   = (const float*)d_in[0];
    const float* Wq  = (const float*)d_in[1];
    const float* Wkv = (const float*)d_in[2];
    const float* Wo  = (const float*)d_in[3];
    const float* bo  = (const float*)d_in[4];
    float* out = (float*)d_out;

    float *q, *kv, *ao;
    cudaGetSymbolAddress((void**)&q,  g_q);
    cudaGetSymbolAddress((void**)&kv, g_kv);
    cudaGetSymbolAddress((void**)&ao, g_ao);

    // Q = x @ Wq   [8192,1024]
    sgemm_k<<<dim3(INNER_ / 128, ROWS_ / 128), 256>>>(x, Wq, nullptr, q,
                                                      ROWS_, INNER_, DIM_);
    // KV = x @ Wkv [8192,2048]
    sgemm_k<<<dim3(2 * INNER_ / 128, ROWS_ / 128), 256>>>(x, Wkv, nullptr, kv,
                                                          ROWS_, 2 * INNER_, DIM_);
    // attention
    flash_attn_k<<<dim3(N_ / 64, H_, B_), 256>>>(q, kv, ao);

    // out = ao @ Wo + bo
    sgemm_k<<<dim3(DIM_ / 128, ROWS_ / 128), 256>>>(ao, Wo, bo, out,
                                                    ROWS_, DIM_, INNER_);
}

// round 4
// speedup vs baseline: 1.5281x; 1.5281x over previous
#include <cuda_runtime.h>
#include <cuda_bf16.h>
#include <math.h>
#include <cstdint>

// Problem constants
#define B_    4
#define N_    2048
#define DIM_  1024
#define H_    16
#define DH_   64
#define INNER_ 1024
#define ROWS_ (B_ * N_)   // 8192
#define QKV_N 3072        // fused [Q|K|V] columns

// ---------------------------------------------------------------------------
// Scratch (device globals — no cudaMalloc allowed)
// ---------------------------------------------------------------------------
__device__ float g_qkv[ROWS_ * QKV_N];              // 96 MB fp32 fused Q|K|V
__device__ float g_ao [ROWS_ * INNER_];             // 32 MB attention out
__device__ __nv_bfloat16 g_xh[ROWS_ * DIM_],  g_xl[ROWS_ * DIM_];
__device__ __nv_bfloat16 g_wth[QKV_N * DIM_], g_wtl[QKV_N * DIM_];   // [n][k]
__device__ __nv_bfloat16 g_woth[DIM_ * INNER_], g_wotl[DIM_ * INNER_];
__device__ __nv_bfloat16 g_aoh[ROWS_ * INNER_], g_aol[ROWS_ * INNER_];

// ---------------------------------------------------------------------------
// helpers
// ---------------------------------------------------------------------------
__device__ __forceinline__ uint32_t smem_u32(const void* p) {
    uint32_t a;
    asm("{ .reg .u64 t; cvta.to.shared.u64 t, %1; cvt.u32.u64 %0, t; }"
        : "=r"(a) : "l"(p));
    return a;
}
#define CP16(dst, src) \
    asm volatile("cp.async.cg.shared.global [%0], [%1], 16;" :: "r"(dst), "l"(src))

__device__ __forceinline__ void ldsm_x4(uint32_t* r, uint32_t addr) {
    asm volatile("ldmatrix.sync.aligned.m8n8.x4.shared.b16 {%0,%1,%2,%3}, [%4];"
                 : "=r"(r[0]), "=r"(r[1]), "=r"(r[2]), "=r"(r[3]) : "r"(addr));
}
__device__ __forceinline__ void mma_bf16(float* d, const uint32_t* a, const uint32_t* b) {
    asm volatile(
        "mma.sync.aligned.m16n8k16.row.col.f32.bf16.bf16.f32 "
        "{%0,%1,%2,%3}, {%4,%5,%6,%7}, {%8,%9}, {%0,%1,%2,%3};"
        : "+f"(d[0]), "+f"(d[1]), "+f"(d[2]), "+f"(d[3])
        : "r"(a[0]), "r"(a[1]), "r"(a[2]), "r"(a[3]), "r"(b[0]), "r"(b[1]));
}

// ---------------------------------------------------------------------------
// fp32 -> (bf16 hi, bf16 lo) element-wise split
// ---------------------------------------------------------------------------
__global__ void conv_split(const float* __restrict__ in,
                           __nv_bfloat16* __restrict__ hi,
                           __nv_bfloat16* __restrict__ lo, int n4)
{
    int i = blockIdx.x * blockDim.x + threadIdx.x;
    if (i >= n4) return;
    float4 v = ((const float4*)in)[i];
    __nv_bfloat16 h0 = __float2bfloat16(v.x), h1 = __float2bfloat16(v.y);
    __nv_bfloat16 h2 = __float2bfloat16(v.z), h3 = __float2bfloat16(v.w);
    __nv_bfloat16 l0 = __float2bfloat16(v.x - __bfloat162float(h0));
    __nv_bfloat16 l1 = __float2bfloat16(v.y - __bfloat162float(h1));
    __nv_bfloat16 l2 = __float2bfloat16(v.z - __bfloat162float(h2));
    __nv_bfloat16 l3 = __float2bfloat16(v.w - __bfloat162float(h3));
    __nv_bfloat162* H = (__nv_bfloat162*)hi;
    __nv_bfloat162* L = (__nv_bfloat162*)lo;
    __nv_bfloat162 a; a.x = h0; a.y = h1; H[i * 2] = a;
    __nv_bfloat162 b; b.x = h2; b.y = h3; H[i * 2 + 1] = b;
    __nv_bfloat162 c; c.x = l0; c.y = l1; L[i * 2] = c;
    __nv_bfloat162 d; d.x = l2; d.y = l3; L[i * 2 + 1] = d;
}

// ---------------------------------------------------------------------------
// W[k][n] fp32 -> Wt[n][k] (bf16 hi/lo), rows [row_off, row_off+Nw), ld=1024
// ---------------------------------------------------------------------------
__global__ void conv_wt(const float* __restrict__ W, int Nw,
                        __nv_bfloat16* __restrict__ outh,
                        __nv_bfloat16* __restrict__ outl, int row_off)
{
    __shared__ float t[32][33];
    const int bn = blockIdx.x * 32, bk = blockIdx.y * 32;
    const int tx = threadIdx.x, ty = threadIdx.y;
#pragma unroll
    for (int i = 0; i < 4; i++)
        t[ty + i * 8][tx] = W[(size_t)(bk + ty + i * 8) * Nw + bn + tx];
    __syncthreads();
#pragma unroll
    for (int i = 0; i < 4; i++) {
        float v = t[tx][ty + i * 8];
        __nv_bfloat16 h = __float2bfloat16(v);
        __nv_bfloat16 l = __float2bfloat16(v - __bfloat162float(h));
        size_t o = (size_t)(row_off + bn + ty + i * 8) * 1024 + bk + tx;
        outh[o] = h; outl[o] = l;
    }
}

// ---------------------------------------------------------------------------
// Split-bf16 mma.sync GEMM: C[M,N] = A[M,1024] * B[N,1024]^T (+bias)
// A given as Ah/Al [M][1024] bf16; B as Bh/Bl [N][1024] bf16 (K contiguous,
// i.e. col-major of [K,N] -> non-trans ldmatrix for the B fragment).
// Tile 128x128x64, 256 thr, 8 warps (2Mx4N, 64x32 each), double-buffered
// cp.async, 3 mma passes (hh, hl, lh).
// ---------------------------------------------------------------------------
#define BKg   64
#define LDS_  72                      // BK + 8 pad (bf16 elems); 144 B/row
#define TILE_B (128 * LDS_ * 2)       // 18432 B per matrix tile
#define STAGE_B (4 * TILE_B)          // Ah Al Bh Bl
#define GEMM_SMEM (2 * STAGE_B)       // 147456 B

__global__ __launch_bounds__(256, 1)
void gemm_mma(const __nv_bfloat16* __restrict__ Ah, const __nv_bfloat16* __restrict__ Al,
              const __nv_bfloat16* __restrict__ Bh, const __nv_bfloat16* __restrict__ Bl,
              const float* __restrict__ bias, float* __restrict__ C,
              int ldC, int Kd)
{
    extern __shared__ char sm[];
    const uint32_t smb = smem_u32(sm);
    const int tid = threadIdx.x, wid = tid >> 5, lane = tid & 31;
    const int m0 = blockIdx.y * 128, n0 = blockIdx.x * 128;
    const int warp_m = (wid >> 2) * 64;    // 0 or 64
    const int warp_n = (wid & 3) * 32;     // 0,32,64,96

    float acc[4][4][4];
#pragma unroll
    for (int a = 0; a < 4; a++)
#pragma unroll
        for (int b = 0; b < 4; b++)
#pragma unroll
            for (int c = 0; c < 4; c++) acc[a][b][c] = 0.f;

    const int n_iters = Kd / BKg;

    auto issue_stage = [&](int buf, int k0) {
        const uint32_t sb = smb + buf * STAGE_B;
#pragma unroll
        for (int p = 0; p < 4; ++p) {
            const int idx = tid + p * 256;       // 0..1023
            const int r = idx >> 3;              // 0..127
            const int c = idx & 7;               // 0..7 (16B chunks)
            const uint32_t so = (uint32_t)r * (LDS_ * 2) + c * 16;
            const size_t goA = (size_t)(m0 + r) * 1024 + k0 + c * 8;
            const size_t goB = (size_t)(n0 + r) * 1024 + k0 + c * 8;
            CP16(sb + so,              (const char*)(Ah + goA));
            CP16(sb + TILE_B + so,     (const char*)(Al + goA));
            CP16(sb + 2 * TILE_B + so, (const char*)(Bh + goB));
            CP16(sb + 3 * TILE_B + so, (const char*)(Bl + goB));
        }
        asm volatile("cp.async.commit_group;" ::: "memory");
    };

    issue_stage(0, 0);

    // ldmatrix per-lane source rows (element coords within a tile)
    const int a_row = warp_m + (lane & 15);
    const int a_col = (lane >> 4) << 3;
    const int b_row = warp_n + (lane & 7) + ((lane & 16) >> 1);
    const int b_col = (lane & 8);

    for (int it = 0; it < n_iters; ++it) {
        if (it + 1 < n_iters) issue_stage((it + 1) & 1, (it + 1) * BKg);
        else asm volatile("cp.async.commit_group;" ::: "memory");
        asm volatile("cp.async.wait_group 1;" ::: "memory");
        __syncthreads();

        const uint32_t sb = smb + (it & 1) * STAGE_B;
        const uint32_t sAh = sb, sAl = sb + TILE_B;
        const uint32_t sBh = sb + 2 * TILE_B, sBl = sb + 3 * TILE_B;

#pragma unroll
        for (int ks = 0; ks < BKg / 16; ++ks) {
            const int koff = ks * 16;
            uint32_t afh[4][4], afl[4][4];   // [mf][4 regs]
            uint32_t bfh[4][2], bfl[4][2];   // [nf][2 regs]
#pragma unroll
            for (int mf = 0; mf < 4; ++mf) {
                const uint32_t ao =
                    (uint32_t)(a_row + mf * 16) * (LDS_ * 2) + (a_col + koff) * 2;
                ldsm_x4(afh[mf], sAh + ao);
                ldsm_x4(afl[mf], sAl + ao);
            }
#pragma unroll
            for (int g = 0; g < 2; ++g) {    // two n16 groups -> 4 nf
                const uint32_t bo =
                    (uint32_t)(b_row + g * 16) * (LDS_ * 2) + (b_col + koff) * 2;
                uint32_t th[4], tl[4];
                ldsm_x4(th, sBh + bo);       // NON-trans: B stored [n][k]
                ldsm_x4(tl, sBl + bo);
                bfh[g * 2][0] = th[0]; bfh[g * 2][1] = th[1];
                bfh[g * 2 + 1][0] = th[2]; bfh[g * 2 + 1][1] = th[3];
                bfl[g * 2][0] = tl[0]; bfl[g * 2][1] = tl[1];
                bfl[g * 2 + 1][0] = tl[2]; bfl[g * 2 + 1][1] = tl[3];
            }
#pragma unroll
            for (int mf = 0; mf < 4; ++mf)
#pragma unroll
                for (int nf = 0; nf < 4; ++nf) {
                    mma_bf16(acc[mf][nf], afh[mf], bfh[nf]);
                    mma_bf16(acc[mf][nf], afh[mf], bfl[nf]);
                    mma_bf16(acc[mf][nf], afl[mf], bfh[nf]);
                }
        }
        __syncthreads();
    }

    // ---- epilogue: fragment layout -> gmem (float2 stores) ----
    const int gid = lane >> 2, tig = lane & 3;
#pragma unroll
    for (int mf = 0; mf < 4; ++mf)
#pragma unroll
        for (int nf = 0; nf < 4; ++nf) {
            const int col = n0 + warp_n + nf * 8 + tig * 2;
            const int row0 = m0 + warp_m + mf * 16 + gid;
            float2 v0 = make_float2(acc[mf][nf][0], acc[mf][nf][1]);
            float2 v1 = make_float2(acc[mf][nf][2], acc[mf][nf][3]);
            if (bias) {
                const float b0 = bias[col], b1 = bias[col + 1];
                v0.x += b0; v0.y += b1; v1.x += b0; v1.y += b1;
            }
            *(float2*)(C + (size_t)row0 * ldC + col) = v0;
            *(float2*)(C + (size_t)(row0 + 8) * ldC + col) = v1;
        }
}

// ---------------------------------------------------------------------------
// Flash attention (causal), fp32, reading fused QKV [8192][3072]
// ---------------------------------------------------------------------------
#define FS 64

__global__ __launch_bounds__(256, 3)
void flash_attn_k(const float* __restrict__ gqkv, float* __restrict__ go)
{
    __shared__ float Qs[DH_ * FS];
    __shared__ float KP[DH_ * FS];
    __shared__ float Vs[64 * FS];

    const int b  = blockIdx.z;
    const int h  = blockIdx.y;
    const int ib = blockIdx.x;
    const int tid = threadIdx.x;
    const int tr = tid >> 4;
    const int tc = tid & 15;
    const int n0 = ib * 64;
    const float scale = 0.125f;

    {
        const int r  = tid >> 2;
        const int d0 = (tid & 3) * 16;
        const float* qp = gqkv + ((size_t)(b * N_ + n0 + r)) * QKV_N + h * DH_;
#pragma unroll
        for (int u = 0; u < 4; u++) {
            float4 v = *(const float4*)(qp + d0 + u * 4);
            const int d = d0 + u * 4;
            Qs[(d + 0) * FS + r] = v.x;
            Qs[(d + 1) * FS + r] = v.y;
            Qs[(d + 2) * FS + r] = v.z;
            Qs[(d + 3) * FS + r] = v.w;
        }
    }

    float acc[4][4];
    float m_i[4], l_i[4];
#pragma unroll
    for (int i = 0; i < 4; i++) {
        m_i[i] = -INFINITY; l_i[i] = 0.f;
#pragma unroll
        for (int j = 0; j < 4; j++) acc[i][j] = 0.f;
    }

    for (int jb = 0; jb <= ib; jb++) {
        const int c0 = jb * 64;
        __syncthreads();
        {
            const int c  = tid >> 2;
            const int d0 = (tid & 3) * 16;
            const float* kp = gqkv + ((size_t)(b * N_ + c0 + c)) * QKV_N + INNER_ + h * DH_;
#pragma unroll
            for (int u = 0; u < 4; u++) {
                float4 kv4 = *(const float4*)(kp + d0 + u * 4);
                const int d = d0 + u * 4;
                KP[(d + 0) * FS + c] = kv4.x;
                KP[(d + 1) * FS + c] = kv4.y;
                KP[(d + 2) * FS + c] = kv4.z;
                KP[(d + 3) * FS + c] = kv4.w;
                float4 vv4 = *(const float4*)(kp + INNER_ + d0 + u * 4);
                *(float4*)(Vs + c * FS + d0 + u * 4) = vv4;
            }
        }
        __syncthreads();

        float s[4][4];
#pragma unroll
        for (int i = 0; i < 4; i++)
#pragma unroll
            for (int j = 0; j < 4; j++) s[i][j] = 0.f;

#pragma unroll 8
        for (int d = 0; d < DH_; d++) {
            float4 qa = *(const float4*)(Qs + d * FS + tr * 4);
            float4 kb = *(const float4*)(KP + d * FS + tc * 4);
            const float* qa_ = &qa.x;
            const float* kb_ = &kb.x;
#pragma unroll
            for (int i = 0; i < 4; i++)
#pragma unroll
                for (int j = 0; j < 4; j++)
                    s[i][j] = fmaf(qa_[i], kb_[j], s[i][j]);
        }

#pragma unroll
        for (int i = 0; i < 4; i++)
#pragma unroll
            for (int j = 0; j < 4; j++) {
                float v = s[i][j] * scale;
                if (jb == ib && (tc * 4 + j) > (tr * 4 + i)) v = -INFINITY;
                s[i][j] = v;
            }

        float mn[4], fac[4];
#pragma unroll
        for (int i = 0; i < 4; i++) {
            float rm = fmaxf(fmaxf(s[i][0], s[i][1]), fmaxf(s[i][2], s[i][3]));
#pragma unroll
            for (int off = 8; off > 0; off >>= 1)
                rm = fmaxf(rm, __shfl_xor_sync(0xffffffffu, rm, off));
            mn[i]  = fmaxf(m_i[i], rm);
            fac[i] = expf(m_i[i] - mn[i]);
        }
#pragma unroll
        for (int i = 0; i < 4; i++) {
            float sum = 0.f;
#pragma unroll
            for (int j = 0; j < 4; j++) {
                s[i][j] = expf(s[i][j] - mn[i]);
                sum += s[i][j];
            }
#pragma unroll
            for (int off = 8; off > 0; off >>= 1)
                sum += __shfl_xor_sync(0xffffffffu, sum, off);
            l_i[i] = l_i[i] * fac[i] + sum;
            m_i[i] = mn[i];
#pragma unroll
            for (int j = 0; j < 4; j++) acc[i][j] *= fac[i];
        }

        __syncthreads();
#pragma unroll
        for (int j = 0; j < 4; j++) {
            float4 p4 = make_float4(s[0][j], s[1][j], s[2][j], s[3][j]);
            *(float4*)(KP + (tc * 4 + j) * FS + tr * 4) = p4;
        }
        __syncthreads();

#pragma unroll 8
        for (int c = 0; c < 64; c++) {
            float4 pa = *(const float4*)(KP + c * FS + tr * 4);
            float4 vb = *(const float4*)(Vs + c * FS + tc * 4);
            const float* pa_ = &pa.x;
            const float* vb_ = &vb.x;
#pragma unroll
            for (int i = 0; i < 4; i++)
#pragma unroll
                for (int j = 0; j < 4; j++)
                    acc[i][j] = fmaf(pa_[i], vb_[j], acc[i][j]);
        }
    }

#pragma unroll
    for (int i = 0; i < 4; i++) {
        const float inv = 1.f / l_i[i];
        const int row = n0 + tr * 4 + i;
        float4 o = make_float4(acc[i][0] * inv, acc[i][1] * inv,
                               acc[i][2] * inv, acc[i][3] * inv);
        *(float4*)(go + ((size_t)(b * N_ + row)) * INNER_ + h * DH_ + tc * 4) = o;
    }
}

// ---------------------------------------------------------------------------
extern "C" void kernel_launch(void* const* d_in, const int* in_sizes, int n_in,
                              void* d_out, int out_size)
{
    const float* x   = (const float*)d_in[0];
    const float* Wq  = (const float*)d_in[1];
    const float* Wkv = (const float*)d_in[2];
    const float* Wo  = (const float*)d_in[3];
    const float* bo  = (const float*)d_in[4];
    float* out = (float*)d_out;

    float *qkv, *ao;
    __nv_bfloat16 *xh, *xl, *wth, *wtl, *woth, *wotl, *aoh, *aol;
    cudaGetSymbolAddress((void**)&qkv,  g_qkv);
    cudaGetSymbolAddress((void**)&ao,   g_ao);
    cudaGetSymbolAddress((void**)&xh,   g_xh);
    cudaGetSymbolAddress((void**)&xl,   g_xl);
    cudaGetSymbolAddress((void**)&wth,  g_wth);
    cudaGetSymbolAddress((void**)&wtl,  g_wtl);
    cudaGetSymbolAddress((void**)&woth, g_woth);
    cudaGetSymbolAddress((void**)&wotl, g_wotl);
    cudaGetSymbolAddress((void**)&aoh,  g_aoh);
    cudaGetSymbolAddress((void**)&aol,  g_aol);

    static bool attr_set = false;
    if (!attr_set) {
        cudaFuncSetAttribute(gemm_mma, cudaFuncAttributeMaxDynamicSharedMemorySize,
                             GEMM_SMEM);
        attr_set = true;
    }

    const int n4x = ROWS_ * DIM_ / 4;
    conv_split<<<(n4x + 255) / 256, 256>>>(x, xh, xl, n4x);
    conv_wt<<<dim3(INNER_ / 32, DIM_ / 32), dim3(32, 8)>>>(Wq,  INNER_,     wth, wtl, 0);
    conv_wt<<<dim3(2 * INNER_ / 32, DIM_ / 32), dim3(32, 8)>>>(Wkv, 2 * INNER_, wth, wtl, 1024);
    conv_wt<<<dim3(DIM_ / 32, INNER_ / 32), dim3(32, 8)>>>(Wo,  DIM_,       woth, wotl, 0);

    // fused QKV projection: [8192,3072] = x(split) @ [Wq|Wkv](split)^T
    gemm_mma<<<dim3(QKV_N / 128, ROWS_ / 128), 256, GEMM_SMEM>>>(
        xh, xl, wth, wtl, nullptr, qkv, QKV_N, DIM_);

    flash_attn_k<<<dim3(N_ / 64, H_, B_), 256>>>(qkv, ao);

    const int n4a = ROWS_ * INNER_ / 4;
    conv_split<<<(n4a + 255) / 256, 256>>>(ao, aoh, aol, n4a);

    gemm_mma<<<dim3(DIM_ / 128, ROWS_ / 128), 256, GEMM_SMEM>>>(
        aoh, aol, woth, wotl, bo, out, DIM_, INNER_);
}

// round 5
// speedup vs baseline: 3.0095x; 1.9694x over previous
#include <cuda_runtime.h>
#include <cuda_bf16.h>
#include <math.h>
#include <cstdint>

// Problem constants
#define B_    4
#define N_    2048
#define DIM_  1024
#define H_    16
#define DH_   64
#define INNER_ 1024
#define ROWS_ (B_ * N_)   // 8192
#define QKV_N 3072        // fused [Q|K|V] columns

// ---------------------------------------------------------------------------
// Scratch (device globals — no cudaMalloc allowed)
// ---------------------------------------------------------------------------
__device__ __nv_bfloat16 g_qkvh[ROWS_ * QKV_N], g_qkvl[ROWS_ * QKV_N]; // 48MB ea
__device__ __nv_bfloat16 g_xh[ROWS_ * DIM_],  g_xl[ROWS_ * DIM_];
__device__ __nv_bfloat16 g_wth[QKV_N * DIM_], g_wtl[QKV_N * DIM_];   // [n][k]
__device__ __nv_bfloat16 g_woth[DIM_ * INNER_], g_wotl[DIM_ * INNER_];
__device__ __nv_bfloat16 g_aoh[ROWS_ * INNER_], g_aol[ROWS_ * INNER_];

// ---------------------------------------------------------------------------
// helpers
// ---------------------------------------------------------------------------
__device__ __forceinline__ uint32_t smem_u32(const void* p) {
    uint32_t a;
    asm("{ .reg .u64 t; cvta.to.shared.u64 t, %1; cvt.u32.u64 %0, t; }"
        : "=r"(a) : "l"(p));
    return a;
}
#define CP16(dst, src) \
    asm volatile("cp.async.cg.shared.global [%0], [%1], 16;" :: "r"(dst), "l"(src))

__device__ __forceinline__ void ldsm_x4(uint32_t* r, uint32_t addr) {
    asm volatile("ldmatrix.sync.aligned.m8n8.x4.shared.b16 {%0,%1,%2,%3}, [%4];"
                 : "=r"(r[0]), "=r"(r[1]), "=r"(r[2]), "=r"(r[3]) : "r"(addr));
}
__device__ __forceinline__ void ldsm_x4t(uint32_t* r, uint32_t addr) {
    asm volatile("ldmatrix.sync.aligned.m8n8.x4.trans.shared.b16 {%0,%1,%2,%3}, [%4];"
                 : "=r"(r[0]), "=r"(r[1]), "=r"(r[2]), "=r"(r[3]) : "r"(addr));
}
__device__ __forceinline__ void mma_bf16(float* d, const uint32_t* a, const uint32_t* b) {
    asm volatile(
        "mma.sync.aligned.m16n8k16.row.col.f32.bf16.bf16.f32 "
        "{%0,%1,%2,%3}, {%4,%5,%6,%7}, {%8,%9}, {%0,%1,%2,%3};"
        : "+f"(d[0]), "+f"(d[1]), "+f"(d[2]), "+f"(d[3])
        : "r"(a[0]), "r"(a[1]), "r"(a[2]), "r"(a[3]), "r"(b[0]), "r"(b[1]));
}
// pack two floats -> bf16x2 (lo -> low half)
__device__ __forceinline__ uint32_t packbf(float lo, float hi) {
    __nv_bfloat162 t = __floats2bfloat162_rn(lo, hi);
    return *reinterpret_cast<uint32_t*>(&t);
}
__device__ __forceinline__ float bflo_f(uint32_t p) { return __uint_as_float(p << 16); }
__device__ __forceinline__ float bfhi_f(uint32_t p) { return __uint_as_float(p & 0xffff0000u); }

// ---------------------------------------------------------------------------
// fp32 -> (bf16 hi, bf16 lo) element-wise split
// ---------------------------------------------------------------------------
__global__ void conv_split(const float* __restrict__ in,
                           __nv_bfloat16* __restrict__ hi,
                           __nv_bfloat16* __restrict__ lo, int n4)
{
    int i = blockIdx.x * blockDim.x + threadIdx.x;
    if (i >= n4) return;
    float4 v = ((const float4*)in)[i];
    __nv_bfloat16 h0 = __float2bfloat16(v.x), h1 = __float2bfloat16(v.y);
    __nv_bfloat16 h2 = __float2bfloat16(v.z), h3 = __float2bfloat16(v.w);
    __nv_bfloat16 l0 = __float2bfloat16(v.x - __bfloat162float(h0));
    __nv_bfloat16 l1 = __float2bfloat16(v.y - __bfloat162float(h1));
    __nv_bfloat16 l2 = __float2bfloat16(v.z - __bfloat162float(h2));
    __nv_bfloat16 l3 = __float2bfloat16(v.w - __bfloat162float(h3));
    __nv_bfloat162* H = (__nv_bfloat162*)hi;
    __nv_bfloat162* L = (__nv_bfloat162*)lo;
    __nv_bfloat162 a; a.x = h0; a.y = h1; H[i * 2] = a;
    __nv_bfloat162 b; b.x = h2; b.y = h3; H[i * 2 + 1] = b;
    __nv_bfloat162 c; c.x = l0; c.y = l1; L[i * 2] = c;
    __nv_bfloat162 d; d.x = l2; d.y = l3; L[i * 2 + 1] = d;
}

// ---------------------------------------------------------------------------
// W[k][n] fp32 -> Wt[n][k] (bf16 hi/lo), rows [row_off, row_off+Nw), ld=1024
// ---------------------------------------------------------------------------
__global__ void conv_wt(const float* __restrict__ W, int Nw,
                        __nv_bfloat16* __restrict__ outh,
                        __nv_bfloat16* __restrict__ outl, int row_off)
{
    __shared__ float t[32][33];
    const int bn = blockIdx.x * 32, bk = blockIdx.y * 32;
    const int tx = threadIdx.x, ty = threadIdx.y;
#pragma unroll
    for (int i = 0; i < 4; i++)
        t[ty + i * 8][tx] = W[(size_t)(bk + ty + i * 8) * Nw + bn + tx];
    __syncthreads();
#pragma unroll
    for (int i = 0; i < 4; i++) {
        float v = t[tx][ty + i * 8];
        __nv_bfloat16 h = __float2bfloat16(v);
        __nv_bfloat16 l = __float2bfloat16(v - __bfloat162float(h));
        size_t o = (size_t)(row_off + bn + ty + i * 8) * 1024 + bk + tx;
        outh[o] = h; outl[o] = l;
    }
}

// ---------------------------------------------------------------------------
// Split-bf16 mma.sync GEMM: C[M,N] = A[M,1024] * B[N,1024]^T (+bias)
// If Ch != null: write split bf16 hi/lo instead of fp32.
// ---------------------------------------------------------------------------
#define BKg   64
#define LDS_  72                      // BK + 8 pad (bf16 elems); 144 B/row
#define TILE_B (128 * LDS_ * 2)       // 18432 B per matrix tile
#define STAGE_B (4 * TILE_B)          // Ah Al Bh Bl
#define GEMM_SMEM (2 * STAGE_B)       // 147456 B

__global__ __launch_bounds__(256, 1)
void gemm_mma(const __nv_bfloat16* __restrict__ Ah, const __nv_bfloat16* __restrict__ Al,
              const __nv_bfloat16* __restrict__ Bh, const __nv_bfloat16* __restrict__ Bl,
              const float* __restrict__ bias, float* __restrict__ C,
              __nv_bfloat16* __restrict__ Ch, __nv_bfloat16* __restrict__ Cl,
              int ldC, int Kd)
{
    extern __shared__ char sm[];
    const uint32_t smb = smem_u32(sm);
    const int tid = threadIdx.x, wid = tid >> 5, lane = tid & 31;
    const int m0 = blockIdx.y * 128, n0 = blockIdx.x * 128;
    const int warp_m = (wid >> 2) * 64;    // 0 or 64
    const int warp_n = (wid & 3) * 32;     // 0,32,64,96

    float acc[4][4][4];
#pragma unroll
    for (int a = 0; a < 4; a++)
#pragma unroll
        for (int b = 0; b < 4; b++)
#pragma unroll
            for (int c = 0; c < 4; c++) acc[a][b][c] = 0.f;

    const int n_iters = Kd / BKg;

    auto issue_stage = [&](int buf, int k0) {
        const uint32_t sb = smb + buf * STAGE_B;
#pragma unroll
        for (int p = 0; p < 4; ++p) {
            const int idx = tid + p * 256;       // 0..1023
            const int r = idx >> 3;              // 0..127
            const int c = idx & 7;               // 0..7 (16B chunks)
            const uint32_t so = (uint32_t)r * (LDS_ * 2) + c * 16;
            const size_t goA = (size_t)(m0 + r) * 1024 + k0 + c * 8;
            const size_t goB = (size_t)(n0 + r) * 1024 + k0 + c * 8;
            CP16(sb + so,              (const char*)(Ah + goA));
            CP16(sb + TILE_B + so,     (const char*)(Al + goA));
            CP16(sb + 2 * TILE_B + so, (const char*)(Bh + goB));
            CP16(sb + 3 * TILE_B + so, (const char*)(Bl + goB));
        }
        asm volatile("cp.async.commit_group;" ::: "memory");
    };

    issue_stage(0, 0);

    const int a_row = warp_m + (lane & 15);
    const int a_col = (lane >> 4) << 3;
    const int b_row = warp_n + (lane & 7) + ((lane & 16) >> 1);
    const int b_col = (lane & 8);

    for (int it = 0; it < n_iters; ++it) {
        if (it + 1 < n_iters) issue_stage((it + 1) & 1, (it + 1) * BKg);
        else asm volatile("cp.async.commit_group;" ::: "memory");
        asm volatile("cp.async.wait_group 1;" ::: "memory");
        __syncthreads();

        const uint32_t sb = smb + (it & 1) * STAGE_B;
        const uint32_t sAh = sb, sAl = sb + TILE_B;
        const uint32_t sBh = sb + 2 * TILE_B, sBl = sb + 3 * TILE_B;

#pragma unroll
        for (int ks = 0; ks < BKg / 16; ++ks) {
            const int koff = ks * 16;
            uint32_t afh[4][4], afl[4][4];
            uint32_t bfh[4][2], bfl[4][2];
#pragma unroll
            for (int mf = 0; mf < 4; ++mf) {
                const uint32_t ao =
                    (uint32_t)(a_row + mf * 16) * (LDS_ * 2) + (a_col + koff) * 2;
                ldsm_x4(afh[mf], sAh + ao);
                ldsm_x4(afl[mf], sAl + ao);
            }
#pragma unroll
            for (int g = 0; g < 2; ++g) {
                const uint32_t bo =
                    (uint32_t)(b_row + g * 16) * (LDS_ * 2) + (b_col + koff) * 2;
                uint32_t th[4], tl[4];
                ldsm_x4(th, sBh + bo);       // NON-trans: B stored [n][k]
                ldsm_x4(tl, sBl + bo);
                bfh[g * 2][0] = th[0]; bfh[g * 2][1] = th[1];
                bfh[g * 2 + 1][0] = th[2]; bfh[g * 2 + 1][1] = th[3];
                bfl[g * 2][0] = tl[0]; bfl[g * 2][1] = tl[1];
                bfl[g * 2 + 1][0] = tl[2]; bfl[g * 2 + 1][1] = tl[3];
            }
#pragma unroll
            for (int mf = 0; mf < 4; ++mf)
#pragma unroll
                for (int nf = 0; nf < 4; ++nf) {
                    mma_bf16(acc[mf][nf], afh[mf], bfh[nf]);
                    mma_bf16(acc[mf][nf], afh[mf], bfl[nf]);
                    mma_bf16(acc[mf][nf], afl[mf], bfh[nf]);
                }
        }
        __syncthreads();
    }

    // ---- epilogue ----
    const int gid = lane >> 2, tig = lane & 3;
#pragma unroll
    for (int mf = 0; mf < 4; ++mf)
#pragma unroll
        for (int nf = 0; nf < 4; ++nf) {
            const int col = n0 + warp_n + nf * 8 + tig * 2;
            const int row0 = m0 + warp_m + mf * 16 + gid;
            if (Ch) {
                // split bf16 output
#pragma unroll
                for (int rr = 0; rr < 2; ++rr) {
                    const float e0 = acc[mf][nf][rr * 2], e1 = acc[mf][nf][rr * 2 + 1];
                    const uint32_t hp = packbf(e0, e1);
                    const uint32_t lp = packbf(e0 - bflo_f(hp), e1 - bfhi_f(hp));
                    const size_t off = (size_t)(row0 + rr * 8) * ldC + col;
                    *(uint32_t*)(Ch + off) = hp;
                    *(uint32_t*)(Cl + off) = lp;
                }
            } else {
                float2 v0 = make_float2(acc[mf][nf][0], acc[mf][nf][1]);
                float2 v1 = make_float2(acc[mf][nf][2], acc[mf][nf][3]);
                if (bias) {
                    const float b0 = bias[col], b1 = bias[col + 1];
                    v0.x += b0; v0.y += b1; v1.x += b0; v1.y += b1;
                }
                *(float2*)(C + (size_t)row0 * ldC + col) = v0;
                *(float2*)(C + (size_t)(row0 + 8) * ldC + col) = v1;
            }
        }
}

// ---------------------------------------------------------------------------
// Flash attention (causal) on tensor cores, split-bf16 everywhere.
// CTA = 128 q rows of one (b,h); 8 warps x 16 rows. Key tiles of 64.
// Smem: Qh,Ql [128x64] + double-buffered Kh,Kl,Vh,Vl [64x64].
// ---------------------------------------------------------------------------
#define AST   72                       // smem row stride in halves
#define QT_B  (128 * AST * 2)          // 18432
#define KT_B  (64 * AST * 2)           // 9216
#define KV_STAGE (4 * KT_B)            // 36864
#define AT_SMEM (2 * QT_B + 2 * KV_STAGE)   // 110592

__global__ __launch_bounds__(256, 1)
void flash_attn_mma(const __nv_bfloat16* __restrict__ qkvh,
                    const __nv_bfloat16* __restrict__ qkvl,
                    __nv_bfloat16* __restrict__ aoh,
                    __nv_bfloat16* __restrict__ aol)
{
    extern __shared__ char sm[];
    const uint32_t smb = smem_u32(sm);
    const uint32_t sQh = smb, sQl = smb + QT_B;
    const uint32_t kvb = smb + 2 * QT_B;

    const int tid = threadIdx.x, wid = tid >> 5, lane = tid & 31;
    const int gid = lane >> 2, tig = lane & 3;
    const int b = blockIdx.z, h = blockIdx.y, ib = blockIdx.x;

    const size_t rowQ0 = (size_t)b * N_ + ib * 128;
    const int colQ = h * DH_;
    const int colK = INNER_ + h * DH_;
    const int colV = 2 * INNER_ + h * DH_;

    // ---- Q loads (hi+lo), committed with first KV group ----
#pragma unroll
    for (int p = 0; p < 4; ++p) {
        const int idx = tid + p * 256;      // 0..1023
        const int r = idx >> 3, c = idx & 7;
        const uint32_t so = (uint32_t)r * (AST * 2) + c * 16;
        const size_t go = (rowQ0 + r) * QKV_N + colQ + c * 8;
        CP16(sQh + so, (const char*)(qkvh + go));
        CP16(sQl + so, (const char*)(qkvl + go));
    }

    auto issue_kv = [&](int jb, int buf) {
        const uint32_t sb = kvb + buf * KV_STAGE;
        const size_t rowK0 = (size_t)b * N_ + jb * 64;
#pragma unroll
        for (int p = 0; p < 2; ++p) {
            const int idx = tid + p * 256;  // 0..511
            const int r = idx >> 3, c = idx & 7;
            const uint32_t so = (uint32_t)r * (AST * 2) + c * 16;
            const size_t gk = (rowK0 + r) * QKV_N + colK + c * 8;
            const size_t gv = (rowK0 + r) * QKV_N + colV + c * 8;
            CP16(sb + so,            (const char*)(qkvh + gk));
            CP16(sb + KT_B + so,     (const char*)(qkvl + gk));
            CP16(sb + 2 * KT_B + so, (const char*)(qkvh + gv));
            CP16(sb + 3 * KT_B + so, (const char*)(qkvl + gv));
        }
        asm volatile("cp.async.commit_group;" ::: "memory");
    };

    issue_kv(0, 0);

    float o[8][4];
#pragma unroll
    for (int i = 0; i < 8; i++)
#pragma unroll
        for (int j = 0; j < 4; j++) o[i][j] = 0.f;
    float m0 = -INFINITY, m1 = -INFINITY, l0 = 0.f, l1 = 0.f;

    // fragment addressing
    const int a_row = wid * 16 + (lane & 15);
    const int a_col = (lane >> 4) << 3;
    const int bk_row = (lane & 7) + ((lane & 16) >> 1);   // K b-frag (non-trans)
    const int bk_col = (lane & 8);
    const int v_row = (lane & 15);                        // V b-frag (trans)
    const int v_col = (lane >> 4) << 3;

    const int row0g = ib * 128 + wid * 16 + gid;          // global q rows
    const int row1g = row0g + 8;
    const int ntiles = 2 * ib + 2;

    for (int jb = 0; jb < ntiles; ++jb) {
        if (jb + 1 < ntiles) issue_kv(jb + 1, (jb + 1) & 1);
        else asm volatile("cp.async.commit_group;" ::: "memory");
        asm volatile("cp.async.wait_group 1;" ::: "memory");
        __syncthreads();

        const uint32_t sb = kvb + (jb & 1) * KV_STAGE;
        const uint32_t sKh = sb, sKl = sb + KT_B;
        const uint32_t sVh = sb + 2 * KT_B, sVl = sb + 3 * KT_B;

        // ---- S = Q K^T (split, 3 passes) ----
        float s[8][4];
#pragma unroll
        for (int i = 0; i < 8; i++)
#pragma unroll
            for (int j = 0; j < 4; j++) s[i][j] = 0.f;

#pragma unroll
        for (int ks = 0; ks < 4; ++ks) {
            uint32_t qh[4], ql[4];
            const uint32_t ao = (uint32_t)a_row * (AST * 2) + (a_col + ks * 16) * 2;
            ldsm_x4(qh, sQh + ao);
            ldsm_x4(ql, sQl + ao);
#pragma unroll
            for (int g = 0; g < 4; ++g) {
                const uint32_t bo =
                    (uint32_t)(g * 16 + bk_row) * (AST * 2) + (ks * 16 + bk_col) * 2;
                uint32_t kh[4], kl[4];
                ldsm_x4(kh, sKh + bo);
                ldsm_x4(kl, sKl + bo);
                mma_bf16(s[g * 2],     qh, kh);
                mma_bf16(s[g * 2],     qh, kl);
                mma_bf16(s[g * 2],     ql, kh);
                mma_bf16(s[g * 2 + 1], qh, kh + 2);
                mma_bf16(s[g * 2 + 1], qh, kl + 2);
                mma_bf16(s[g * 2 + 1], ql, kh + 2);
            }
        }

        // ---- scale + causal mask ----
#pragma unroll
        for (int nf = 0; nf < 8; ++nf)
#pragma unroll
            for (int e = 0; e < 4; ++e) s[nf][e] *= 0.125f;
        if (jb >= 2 * ib) {
#pragma unroll
            for (int nf = 0; nf < 8; ++nf) {
                const int col = jb * 64 + nf * 8 + tig * 2;
                if (col     > row0g) s[nf][0] = -INFINITY;
                if (col + 1 > row0g) s[nf][1] = -INFINITY;
                if (col     > row1g) s[nf][2] = -INFINITY;
                if (col + 1 > row1g) s[nf][3] = -INFINITY;
            }
        }

        // ---- online softmax ----
        float mx0 = -INFINITY, mx1 = -INFINITY;
#pragma unroll
        for (int nf = 0; nf < 8; ++nf) {
            mx0 = fmaxf(mx0, fmaxf(s[nf][0], s[nf][1]));
            mx1 = fmaxf(mx1, fmaxf(s[nf][2], s[nf][3]));
        }
        mx0 = fmaxf(mx0, __shfl_xor_sync(0xffffffffu, mx0, 1));
        mx0 = fmaxf(mx0, __shfl_xor_sync(0xffffffffu, mx0, 2));
        mx1 = fmaxf(mx1, __shfl_xor_sync(0xffffffffu, mx1, 1));
        mx1 = fmaxf(mx1, __shfl_xor_sync(0xffffffffu, mx1, 2));
        const float nm0 = fmaxf(m0, mx0), nm1 = fmaxf(m1, mx1);
        const float fac0 = __expf(m0 - nm0), fac1 = __expf(m1 - nm1);
        m0 = nm0; m1 = nm1;

        float sum0 = 0.f, sum1 = 0.f;
#pragma unroll
        for (int nf = 0; nf < 8; ++nf) {
            s[nf][0] = __expf(s[nf][0] - nm0);
            s[nf][1] = __expf(s[nf][1] - nm0);
            s[nf][2] = __expf(s[nf][2] - nm1);
            s[nf][3] = __expf(s[nf][3] - nm1);
            sum0 += s[nf][0] + s[nf][1];
            sum1 += s[nf][2] + s[nf][3];
        }
        sum0 += __shfl_xor_sync(0xffffffffu, sum0, 1);
        sum0 += __shfl_xor_sync(0xffffffffu, sum0, 2);
        sum1 += __shfl_xor_sync(0xffffffffu, sum1, 1);
        sum1 += __shfl_xor_sync(0xffffffffu, sum1, 2);
        l0 = l0 * fac0 + sum0;
        l1 = l1 * fac1 + sum1;
#pragma unroll
        for (int nf = 0; nf < 8; ++nf) {
            o[nf][0] *= fac0; o[nf][1] *= fac0;
            o[nf][2] *= fac1; o[nf][3] *= fac1;
        }

        // ---- O += P V (split, 3 passes); P repacked C-frag -> A-frag ----
#pragma unroll
        for (int kb = 0; kb < 4; ++kb) {
            uint32_t ph[4], pl[4];
#pragma unroll
            for (int half = 0; half < 2; ++half) {
                const float* pp = s[2 * kb + half];
                const uint32_t h01 = packbf(pp[0], pp[1]);
                const uint32_t h23 = packbf(pp[2], pp[3]);
                const uint32_t l01 = packbf(pp[0] - bflo_f(h01), pp[1] - bfhi_f(h01));
                const uint32_t l23 = packbf(pp[2] - bflo_f(h23), pp[3] - bfhi_f(h23));
                ph[half * 2] = h01; ph[half * 2 + 1] = h23;
                pl[half * 2] = l01; pl[half * 2 + 1] = l23;
            }
#pragma unroll
            for (int g = 0; g < 4; ++g) {
                const uint32_t bo =
                    (uint32_t)(kb * 16 + v_row) * (AST * 2) + (g * 16 + v_col) * 2;
                uint32_t vh[4], vl[4];
                ldsm_x4t(vh, sVh + bo);
                ldsm_x4t(vl, sVl + bo);
                mma_bf16(o[g * 2],     ph, vh);
                mma_bf16(o[g * 2],     ph, vl);
                mma_bf16(o[g * 2],     pl, vh);
                mma_bf16(o[g * 2 + 1], ph, vh + 2);
                mma_bf16(o[g * 2 + 1], ph, vl + 2);
                mma_bf16(o[g * 2 + 1], pl, vh + 2);
            }
        }
        __syncthreads();
    }

    // ---- epilogue: normalize, split to bf16 hi/lo, store ----
    const float inv0 = 1.f / l0, inv1 = 1.f / l1;
    const size_t gr0 = (size_t)b * N_ + ib * 128 + wid * 16 + gid;
#pragma unroll
    for (int nf = 0; nf < 8; ++nf) {
        const int col = h * DH_ + nf * 8 + tig * 2;
        const float e0 = o[nf][0] * inv0, e1 = o[nf][1] * inv0;
        const float e2 = o[nf][2] * inv1, e3 = o[nf][3] * inv1;
        const uint32_t hp0 = packbf(e0, e1);
        const uint32_t lp0 = packbf(e0 - bflo_f(hp0), e1 - bfhi_f(hp0));
        const uint32_t hp1 = packbf(e2, e3);
        const uint32_t lp1 = packbf(e2 - bflo_f(hp1), e3 - bfhi_f(hp1));
        *(uint32_t*)(aoh + gr0 * INNER_ + col) = hp0;
        *(uint32_t*)(aol + gr0 * INNER_ + col) = lp0;
        *(uint32_t*)(aoh + (gr0 + 8) * INNER_ + col) = hp1;
        *(uint32_t*)(aol + (gr0 + 8) * INNER_ + col) = lp1;
    }
}

// ---------------------------------------------------------------------------
extern "C" void kernel_launch(void* const* d_in, const int* in_sizes, int n_in,
                              void* d_out, int out_size)
{
    const float* x   = (const float*)d_in[0];
    const float* Wq  = (const float*)d_in[1];
    const float* Wkv = (const float*)d_in[2];
    const float* Wo  = (const float*)d_in[3];
    const float* bo  = (const float*)d_in[4];
    float* out = (float*)d_out;

    __nv_bfloat16 *qkvh, *qkvl, *xh, *xl, *wth, *wtl, *woth, *wotl, *aoh, *aol;
    cudaGetSymbolAddress((void**)&qkvh, g_qkvh);
    cudaGetSymbolAddress((void**)&qkvl, g_qkvl);
    cudaGetSymbolAddress((void**)&xh,   g_xh);
    cudaGetSymbolAddress((void**)&xl,   g_xl);
    cudaGetSymbolAddress((void**)&wth,  g_wth);
    cudaGetSymbolAddress((void**)&wtl,  g_wtl);
    cudaGetSymbolAddress((void**)&woth, g_woth);
    cudaGetSymbolAddress((void**)&wotl, g_wotl);
    cudaGetSymbolAddress((void**)&aoh,  g_aoh);
    cudaGetSymbolAddress((void**)&aol,  g_aol);

    static bool attr_set = false;
    if (!attr_set) {
        cudaFuncSetAttribute(gemm_mma, cudaFuncAttributeMaxDynamicSharedMemorySize,
                             GEMM_SMEM);
        cudaFuncSetAttribute(flash_attn_mma, cudaFuncAttributeMaxDynamicSharedMemorySize,
                             AT_SMEM);
        attr_set = true;
    }

    const int n4x = ROWS_ * DIM_ / 4;
    conv_split<<<(n4x + 255) / 256, 256>>>(x, xh, xl, n4x);
    conv_wt<<<dim3(INNER_ / 32, DIM_ / 32), dim3(32, 8)>>>(Wq,  INNER_,     wth, wtl, 0);
    conv_wt<<<dim3(2 * INNER_ / 32, DIM_ / 32), dim3(32, 8)>>>(Wkv, 2 * INNER_, wth, wtl, 1024);
    conv_wt<<<dim3(DIM_ / 32, INNER_ / 32), dim3(32, 8)>>>(Wo,  DIM_,       woth, wotl, 0);

    // fused QKV projection -> split bf16 output
    gemm_mma<<<dim3(QKV_N / 128, ROWS_ / 128), 256, GEMM_SMEM>>>(
        xh, xl, wth, wtl, nullptr, nullptr, qkvh, qkvl, QKV_N, DIM_);

    // tensor-core flash attention -> split bf16 output
    flash_attn_mma<<<dim3(N_ / 128, H_, B_), 256, AT_SMEM>>>(qkvh, qkvl, aoh, aol);

    // out = ao @ Wo + bo (fp32 output)
    gemm_mma<<<dim3(DIM_ / 128, ROWS_ / 128), 256, GEMM_SMEM>>>(
        aoh, aol, woth, wotl, bo, out, nullptr, nullptr, DIM_, INNER_);
}

// round 6
// speedup vs baseline: 3.0717x; 1.0207x over previous
#include <cuda_runtime.h>
#include <cuda_bf16.h>
#include <math.h>
#include <cstdint>

// Problem constants
#define B_    4
#define N_    2048
#define DIM_  1024
#define H_    16
#define DH_   64
#define INNER_ 1024
#define ROWS_ (B_ * N_)   // 8192
#define QKV_N 3072        // fused [Q|K|V] columns

// ---------------------------------------------------------------------------
// Scratch (device globals — no cudaMalloc allowed)
// ---------------------------------------------------------------------------
__device__ __nv_bfloat16 g_qkvh[ROWS_ * QKV_N], g_qkvl[ROWS_ * QKV_N]; // 48MB ea
__device__ __nv_bfloat16 g_xh[ROWS_ * DIM_],  g_xl[ROWS_ * DIM_];
__device__ __nv_bfloat16 g_wth[QKV_N * DIM_], g_wtl[QKV_N * DIM_];   // [n][k]
__device__ __nv_bfloat16 g_woth[DIM_ * INNER_], g_wotl[DIM_ * INNER_];
__device__ __nv_bfloat16 g_aoh[ROWS_ * INNER_], g_aol[ROWS_ * INNER_];

// ---------------------------------------------------------------------------
// helpers
// ---------------------------------------------------------------------------
__device__ __forceinline__ uint32_t smem_u32(const void* p) {
    uint32_t a;
    asm("{ .reg .u64 t; cvta.to.shared.u64 t, %1; cvt.u32.u64 %0, t; }"
        : "=r"(a) : "l"(p));
    return a;
}
#define CP16(dst, src) \
    asm volatile("cp.async.cg.shared.global [%0], [%1], 16;" :: "r"(dst), "l"(src))

__device__ __forceinline__ void ldsm_x4(uint32_t* r, uint32_t addr) {
    asm volatile("ldmatrix.sync.aligned.m8n8.x4.shared.b16 {%0,%1,%2,%3}, [%4];"
                 : "=r"(r[0]), "=r"(r[1]), "=r"(r[2]), "=r"(r[3]) : "r"(addr));
}
__device__ __forceinline__ void ldsm_x4t(uint32_t* r, uint32_t addr) {
    asm volatile("ldmatrix.sync.aligned.m8n8.x4.trans.shared.b16 {%0,%1,%2,%3}, [%4];"
                 : "=r"(r[0]), "=r"(r[1]), "=r"(r[2]), "=r"(r[3]) : "r"(addr));
}
__device__ __forceinline__ void mma_bf16(float* d, const uint32_t* a, const uint32_t* b) {
    asm volatile(
        "mma.sync.aligned.m16n8k16.row.col.f32.bf16.bf16.f32 "
        "{%0,%1,%2,%3}, {%4,%5,%6,%7}, {%8,%9}, {%0,%1,%2,%3};"
        : "+f"(d[0]), "+f"(d[1]), "+f"(d[2]), "+f"(d[3])
        : "r"(a[0]), "r"(a[1]), "r"(a[2]), "r"(a[3]), "r"(b[0]), "r"(b[1]));
}
// pack two floats -> bf16x2 (lo -> low half)
__device__ __forceinline__ uint32_t packbf(float lo, float hi) {
    __nv_bfloat162 t = __floats2bfloat162_rn(lo, hi);
    return *reinterpret_cast<uint32_t*>(&t);
}
__device__ __forceinline__ float bflo_f(uint32_t p) { return __uint_as_float(p << 16); }
__device__ __forceinline__ float bfhi_f(uint32_t p) { return __uint_as_float(p & 0xffff0000u); }

// ---------------------------------------------------------------------------
// fp32 -> (bf16 hi, bf16 lo) element-wise split
// ---------------------------------------------------------------------------
__global__ void conv_split(const float* __restrict__ in,
                           __nv_bfloat16* __restrict__ hi,
                           __nv_bfloat16* __restrict__ lo, int n4)
{
    int i = blockIdx.x * blockDim.x + threadIdx.x;
    if (i >= n4) return;
    float4 v = ((const float4*)in)[i];
    __nv_bfloat16 h0 = __float2bfloat16(v.x), h1 = __float2bfloat16(v.y);
    __nv_bfloat16 h2 = __float2bfloat16(v.z), h3 = __float2bfloat16(v.w);
    __nv_bfloat16 l0 = __float2bfloat16(v.x - __bfloat162float(h0));
    __nv_bfloat16 l1 = __float2bfloat16(v.y - __bfloat162float(h1));
    __nv_bfloat16 l2 = __float2bfloat16(v.z - __bfloat162float(h2));
    __nv_bfloat16 l3 = __float2bfloat16(v.w - __bfloat162float(h3));
    __nv_bfloat162* H = (__nv_bfloat162*)hi;
    __nv_bfloat162* L = (__nv_bfloat162*)lo;
    __nv_bfloat162 a; a.x = h0; a.y = h1; H[i * 2] = a;
    __nv_bfloat162 b; b.x = h2; b.y = h3; H[i * 2 + 1] = b;
    __nv_bfloat162 c; c.x = l0; c.y = l1; L[i * 2] = c;
    __nv_bfloat162 d; d.x = l2; d.y = l3; L[i * 2 + 1] = d;
}

// ---------------------------------------------------------------------------
// W[k][n] fp32 -> Wt[n][k] (bf16 hi/lo), rows [row_off, row_off+Nw), ld=1024
// ---------------------------------------------------------------------------
__global__ void conv_wt(const float* __restrict__ W, int Nw,
                        __nv_bfloat16* __restrict__ outh,
                        __nv_bfloat16* __restrict__ outl, int row_off)
{
    __shared__ float t[32][33];
    const int bn = blockIdx.x * 32, bk = blockIdx.y * 32;
    const int tx = threadIdx.x, ty = threadIdx.y;
#pragma unroll
    for (int i = 0; i < 4; i++)
        t[ty + i * 8][tx] = W[(size_t)(bk + ty + i * 8) * Nw + bn + tx];
    __syncthreads();
#pragma unroll
    for (int i = 0; i < 4; i++) {
        float v = t[tx][ty + i * 8];
        __nv_bfloat16 h = __float2bfloat16(v);
        __nv_bfloat16 l = __float2bfloat16(v - __bfloat162float(h));
        size_t o = (size_t)(row_off + bn + ty + i * 8) * 1024 + bk + tx;
        outh[o] = h; outl[o] = l;
    }
}

// ---------------------------------------------------------------------------
// Split-bf16 mma.sync GEMM: C[M,N] = A[M,1024] * B[N,1024]^T (+bias)
// 3-stage cp.async pipeline, one __syncthreads per K-chunk.
// If Ch != null: write split bf16 hi/lo instead of fp32.
// ---------------------------------------------------------------------------
#define BKg   64
#define LDS_  72                      // BK + 8 pad (bf16 elems); 144 B/row
#define TILE_B (128 * LDS_ * 2)       // 18432 B per matrix tile
#define STAGE_B (4 * TILE_B)          // Ah Al Bh Bl = 73728
#define GEMM_SMEM (3 * STAGE_B)       // 221184 B

__global__ __launch_bounds__(256, 1)
void gemm_mma(const __nv_bfloat16* __restrict__ Ah, const __nv_bfloat16* __restrict__ Al,
              const __nv_bfloat16* __restrict__ Bh, const __nv_bfloat16* __restrict__ Bl,
              const float* __restrict__ bias, float* __restrict__ C,
              __nv_bfloat16* __restrict__ Ch, __nv_bfloat16* __restrict__ Cl,
              int ldC, int Kd)
{
    extern __shared__ char sm[];
    const uint32_t smb = smem_u32(sm);
    const int tid = threadIdx.x, wid = tid >> 5, lane = tid & 31;
    const int m0 = blockIdx.y * 128, n0 = blockIdx.x * 128;
    const int warp_m = (wid >> 2) * 64;    // 0 or 64
    const int warp_n = (wid & 3) * 32;     // 0,32,64,96

    float acc[4][4][4];
#pragma unroll
    for (int a = 0; a < 4; a++)
#pragma unroll
        for (int b = 0; b < 4; b++)
#pragma unroll
            for (int c = 0; c < 4; c++) acc[a][b][c] = 0.f;

    const int n_iters = Kd / BKg;

    auto issue_stage = [&](int buf, int k0) {
        const uint32_t sb = smb + buf * STAGE_B;
#pragma unroll
        for (int p = 0; p < 4; ++p) {
            const int idx = tid + p * 256;       // 0..1023
            const int r = idx >> 3;              // 0..127
            const int c = idx & 7;               // 0..7 (16B chunks)
            const uint32_t so = (uint32_t)r * (LDS_ * 2) + c * 16;
            const size_t goA = (size_t)(m0 + r) * 1024 + k0 + c * 8;
            const size_t goB = (size_t)(n0 + r) * 1024 + k0 + c * 8;
            CP16(sb + so,              (const char*)(Ah + goA));
            CP16(sb + TILE_B + so,     (const char*)(Al + goA));
            CP16(sb + 2 * TILE_B + so, (const char*)(Bh + goB));
            CP16(sb + 3 * TILE_B + so, (const char*)(Bl + goB));
        }
        asm volatile("cp.async.commit_group;" ::: "memory");
    };

    issue_stage(0, 0);
    issue_stage(1, BKg);

    const int a_row = warp_m + (lane & 15);
    const int a_col = (lane >> 4) << 3;
    const int b_row = warp_n + (lane & 7) + ((lane & 16) >> 1);
    const int b_col = (lane & 8);

    for (int it = 0; it < n_iters; ++it) {
        asm volatile("cp.async.wait_group 1;" ::: "memory");
        __syncthreads();
        if (it + 2 < n_iters) issue_stage((it + 2) % 3, (it + 2) * BKg);

        const uint32_t sb = smb + (it % 3) * STAGE_B;
        const uint32_t sAh = sb, sAl = sb + TILE_B;
        const uint32_t sBh = sb + 2 * TILE_B, sBl = sb + 3 * TILE_B;

#pragma unroll
        for (int ks = 0; ks < BKg / 16; ++ks) {
            const int koff = ks * 16;
            uint32_t afh[4][4], afl[4][4];
            uint32_t bfh[4][2], bfl[4][2];
#pragma unroll
            for (int mf = 0; mf < 4; ++mf) {
                const uint32_t ao =
                    (uint32_t)(a_row + mf * 16) * (LDS_ * 2) + (a_col + koff) * 2;
                ldsm_x4(afh[mf], sAh + ao);
                ldsm_x4(afl[mf], sAl + ao);
            }
#pragma unroll
            for (int g = 0; g < 2; ++g) {
                const uint32_t bo =
                    (uint32_t)(b_row + g * 16) * (LDS_ * 2) + (b_col + koff) * 2;
                uint32_t th[4], tl[4];
                ldsm_x4(th, sBh + bo);       // NON-trans: B stored [n][k]
                ldsm_x4(tl, sBl + bo);
                bfh[g * 2][0] = th[0]; bfh[g * 2][1] = th[1];
                bfh[g * 2 + 1][0] = th[2]; bfh[g * 2 + 1][1] = th[3];
                bfl[g * 2][0] = tl[0]; bfl[g * 2][1] = tl[1];
                bfl[g * 2 + 1][0] = tl[2]; bfl[g * 2 + 1][1] = tl[3];
            }
#pragma unroll
            for (int mf = 0; mf < 4; ++mf)
#pragma unroll
                for (int nf = 0; nf < 4; ++nf) {
                    mma_bf16(acc[mf][nf], afh[mf], bfh[nf]);
                    mma_bf16(acc[mf][nf], afh[mf], bfl[nf]);
                    mma_bf16(acc[mf][nf], afl[mf], bfh[nf]);
                }
        }
    }

    // ---- epilogue ----
    const int gid = lane >> 2, tig = lane & 3;
#pragma unroll
    for (int mf = 0; mf < 4; ++mf)
#pragma unroll
        for (int nf = 0; nf < 4; ++nf) {
            const int col = n0 + warp_n + nf * 8 + tig * 2;
            const int row0 = m0 + warp_m + mf * 16 + gid;
            if (Ch) {
                // split bf16 output
#pragma unroll
                for (int rr = 0; rr < 2; ++rr) {
                    const float e0 = acc[mf][nf][rr * 2], e1 = acc[mf][nf][rr * 2 + 1];
                    const uint32_t hp = packbf(e0, e1);
                    const uint32_t lp = packbf(e0 - bflo_f(hp), e1 - bfhi_f(hp));
                    const size_t off = (size_t)(row0 + rr * 8) * ldC + col;
                    *(uint32_t*)(Ch + off) = hp;
                    *(uint32_t*)(Cl + off) = lp;
                }
            } else {
                float2 v0 = make_float2(acc[mf][nf][0], acc[mf][nf][1]);
                float2 v1 = make_float2(acc[mf][nf][2], acc[mf][nf][3]);
                if (bias) {
                    const float b0 = bias[col], b1 = bias[col + 1];
                    v0.x += b0; v0.y += b1; v1.x += b0; v1.y += b1;
                }
                *(float2*)(C + (size_t)row0 * ldC + col) = v0;
                *(float2*)(C + (size_t)(row0 + 8) * ldC + col) = v1;
            }
        }
}

// ---------------------------------------------------------------------------
// Flash attention (causal) on tensor cores, split-bf16, 3-stage KV pipeline.
// CTA = 128 q rows of one (b,h); 8 warps x 16 rows. Key tiles of 64.
// ib reversed (longest CTAs first) for causal load balance.
// ---------------------------------------------------------------------------
#define AST   72                       // smem row stride in halves
#define QT_B  (128 * AST * 2)          // 18432
#define KT_B  (64 * AST * 2)           // 9216
#define KV_STAGE (4 * KT_B)            // 36864
#define AT_SMEM (2 * QT_B + 3 * KV_STAGE)   // 147456

__global__ __launch_bounds__(256, 1)
void flash_attn_mma(const __nv_bfloat16* __restrict__ qkvh,
                    const __nv_bfloat16* __restrict__ qkvl,
                    __nv_bfloat16* __restrict__ aoh,
                    __nv_bfloat16* __restrict__ aol)
{
    extern __shared__ char sm[];
    const uint32_t smb = smem_u32(sm);
    const uint32_t sQh = smb, sQl = smb + QT_B;
    const uint32_t kvb = smb + 2 * QT_B;

    const int tid = threadIdx.x, wid = tid >> 5, lane = tid & 31;
    const int gid = lane >> 2, tig = lane & 3;
    const int b = blockIdx.z, h = blockIdx.y;
    const int ib = gridDim.x - 1 - blockIdx.x;   // longest CTAs scheduled first

    const size_t rowQ0 = (size_t)b * N_ + ib * 128;
    const int colQ = h * DH_;
    const int colK = INNER_ + h * DH_;
    const int colV = 2 * INNER_ + h * DH_;

    // ---- Q loads (hi+lo), committed with first KV group ----
#pragma unroll
    for (int p = 0; p < 4; ++p) {
        const int idx = tid + p * 256;      // 0..1023
        const int r = idx >> 3, c = idx & 7;
        const uint32_t so = (uint32_t)r * (AST * 2) + c * 16;
        const size_t go = (rowQ0 + r) * QKV_N + colQ + c * 8;
        CP16(sQh + so, (const char*)(qkvh + go));
        CP16(sQl + so, (const char*)(qkvl + go));
    }

    auto issue_kv = [&](int jb, int buf) {
        const uint32_t sb = kvb + buf * KV_STAGE;
        const size_t rowK0 = (size_t)b * N_ + jb * 64;
#pragma unroll
        for (int p = 0; p < 2; ++p) {
            const int idx = tid + p * 256;  // 0..511
            const int r = idx >> 3, c = idx & 7;
            const uint32_t so = (uint32_t)r * (AST * 2) + c * 16;
            const size_t gk = (rowK0 + r) * QKV_N + colK + c * 8;
            const size_t gv = (rowK0 + r) * QKV_N + colV + c * 8;
            CP16(sb + so,            (const char*)(qkvh + gk));
            CP16(sb + KT_B + so,     (const char*)(qkvl + gk));
            CP16(sb + 2 * KT_B + so, (const char*)(qkvh + gv));
            CP16(sb + 3 * KT_B + so, (const char*)(qkvl + gv));
        }
        asm volatile("cp.async.commit_group;" ::: "memory");
    };

    issue_kv(0, 0);
    issue_kv(1, 1);

    float o[8][4];
#pragma unroll
    for (int i = 0; i < 8; i++)
#pragma unroll
        for (int j = 0; j < 4; j++) o[i][j] = 0.f;
    float m0 = -INFINITY, m1 = -INFINITY, l0 = 0.f, l1 = 0.f;

    // fragment addressing
    const int a_row = wid * 16 + (lane & 15);
    const int a_col = (lane >> 4) << 3;
    const int bk_row = (lane & 7) + ((lane & 16) >> 1);   // K b-frag (non-trans)
    const int bk_col = (lane & 8);
    const int v_row = (lane & 15);                        // V b-frag (trans)
    const int v_col = (lane >> 4) << 3;

    const int row0g = ib * 128 + wid * 16 + gid;          // global q rows
    const int row1g = row0g + 8;
    const int ntiles = 2 * ib + 2;

    for (int jb = 0; jb < ntiles; ++jb) {
        asm volatile("cp.async.wait_group 1;" ::: "memory");
        __syncthreads();
        if (jb + 2 < ntiles) issue_kv(jb + 2, (jb + 2) % 3);

        const uint32_t sb = kvb + (jb % 3) * KV_STAGE;
        const uint32_t sKh = sb, sKl = sb + KT_B;
        const uint32_t sVh = sb + 2 * KT_B, sVl = sb + 3 * KT_B;

        // ---- S = Q K^T (split, 3 passes) ----
        float s[8][4];
#pragma unroll
        for (int i = 0; i < 8; i++)
#pragma unroll
            for (int j = 0; j < 4; j++) s[i][j] = 0.f;

#pragma unroll
        for (int ks = 0; ks < 4; ++ks) {
            uint32_t qh[4], ql[4];
            const uint32_t ao = (uint32_t)a_row * (AST * 2) + (a_col + ks * 16) * 2;
            ldsm_x4(qh, sQh + ao);
            ldsm_x4(ql, sQl + ao);
#pragma unroll
            for (int g = 0; g < 4; ++g) {
                const uint32_t bo =
                    (uint32_t)(g * 16 + bk_row) * (AST * 2) + (ks * 16 + bk_col) * 2;
                uint32_t kh[4], kl[4];
                ldsm_x4(kh, sKh + bo);
                ldsm_x4(kl, sKl + bo);
                mma_bf16(s[g * 2],     qh, kh);
                mma_bf16(s[g * 2],     qh, kl);
                mma_bf16(s[g * 2],     ql, kh);
                mma_bf16(s[g * 2 + 1], qh, kh + 2);
                mma_bf16(s[g * 2 + 1], qh, kl + 2);
                mma_bf16(s[g * 2 + 1], ql, kh + 2);
            }
        }

        // ---- scale + causal mask ----
#pragma unroll
        for (int nf = 0; nf < 8; ++nf)
#pragma unroll
            for (int e = 0; e < 4; ++e) s[nf][e] *= 0.125f;
        if (jb >= 2 * ib) {
#pragma unroll
            for (int nf = 0; nf < 8; ++nf) {
                const int col = jb * 64 + nf * 8 + tig * 2;
                if (col     > row0g) s[nf][0] = -INFINITY;
                if (col + 1 > row0g) s[nf][1] = -INFINITY;
                if (col     > row1g) s[nf][2] = -INFINITY;
                if (col + 1 > row1g) s[nf][3] = -INFINITY;
            }
        }

        // ---- online softmax ----
        float mx0 = -INFINITY, mx1 = -INFINITY;
#pragma unroll
        for (int nf = 0; nf < 8; ++nf) {
            mx0 = fmaxf(mx0, fmaxf(s[nf][0], s[nf][1]));
            mx1 = fmaxf(mx1, fmaxf(s[nf][2], s[nf][3]));
        }
        mx0 = fmaxf(mx0, __shfl_xor_sync(0xffffffffu, mx0, 1));
        mx0 = fmaxf(mx0, __shfl_xor_sync(0xffffffffu, mx0, 2));
        mx1 = fmaxf(mx1, __shfl_xor_sync(0xffffffffu, mx1, 1));
        mx1 = fmaxf(mx1, __shfl_xor_sync(0xffffffffu, mx1, 2));
        const float nm0 = fmaxf(m0, mx0), nm1 = fmaxf(m1, mx1);
        const float fac0 = __expf(m0 - nm0), fac1 = __expf(m1 - nm1);
        m0 = nm0; m1 = nm1;

        float sum0 = 0.f, sum1 = 0.f;
#pragma unroll
        for (int nf = 0; nf < 8; ++nf) {
            s[nf][0] = __expf(s[nf][0] - nm0);
            s[nf][1] = __expf(s[nf][1] - nm0);
            s[nf][2] = __expf(s[nf][2] - nm1);
            s[nf][3] = __expf(s[nf][3] - nm1);
            sum0 += s[nf][0] + s[nf][1];
            sum1 += s[nf][2] + s[nf][3];
        }
        sum0 += __shfl_xor_sync(0xffffffffu, sum0, 1);
        sum0 += __shfl_xor_sync(0xffffffffu, sum0, 2);
        sum1 += __shfl_xor_sync(0xffffffffu, sum1, 1);
        sum1 += __shfl_xor_sync(0xffffffffu, sum1, 2);
        l0 = l0 * fac0 + sum0;
        l1 = l1 * fac1 + sum1;
#pragma unroll
        for (int nf = 0; nf < 8; ++nf) {
            o[nf][0] *= fac0; o[nf][1] *= fac0;
            o[nf][2] *= fac1; o[nf][3] *= fac1;
        }

        // ---- O += P V (split, 3 passes); P repacked C-frag -> A-frag ----
#pragma unroll
        for (int kb = 0; kb < 4; ++kb) {
            uint32_t ph[4], pl[4];
#pragma unroll
            for (int half = 0; half < 2; ++half) {
                const float* pp = s[2 * kb + half];
                const uint32_t h01 = packbf(pp[0], pp[1]);
                const uint32_t h23 = packbf(pp[2], pp[3]);
                const uint32_t l01 = packbf(pp[0] - bflo_f(h01), pp[1] - bfhi_f(h01));
                const uint32_t l23 = packbf(pp[2] - bflo_f(h23), pp[3] - bfhi_f(h23));
                ph[half * 2] = h01; ph[half * 2 + 1] = h23;
                pl[half * 2] = l01; pl[half * 2 + 1] = l23;
            }
#pragma unroll
            for (int g = 0; g < 4; ++g) {
                const uint32_t bo =
                    (uint32_t)(kb * 16 + v_row) * (AST * 2) + (g * 16 + v_col) * 2;
                uint32_t vh[4], vl[4];
                ldsm_x4t(vh, sVh + bo);
                ldsm_x4t(vl, sVl + bo);
                mma_bf16(o[g * 2],     ph, vh);
                mma_bf16(o[g * 2],     ph, vl);
                mma_bf16(o[g * 2],     pl, vh);
                mma_bf16(o[g * 2 + 1], ph, vh + 2);
                mma_bf16(o[g * 2 + 1], ph, vl + 2);
                mma_bf16(o[g * 2 + 1], pl, vh + 2);
            }
        }
    }

    // ---- epilogue: normalize, split to bf16 hi/lo, store ----
    const float inv0 = 1.f / l0, inv1 = 1.f / l1;
    const size_t gr0 = (size_t)b * N_ + ib * 128 + wid * 16 + gid;
#pragma unroll
    for (int nf = 0; nf < 8; ++nf) {
        const int col = h * DH_ + nf * 8 + tig * 2;
        const float e0 = o[nf][0] * inv0, e1 = o[nf][1] * inv0;
        const float e2 = o[nf][2] * inv1, e3 = o[nf][3] * inv1;
        const uint32_t hp0 = packbf(e0, e1);
        const uint32_t lp0 = packbf(e0 - bflo_f(hp0), e1 - bfhi_f(hp0));
        const uint32_t hp1 = packbf(e2, e3);
        const uint32_t lp1 = packbf(e2 - bflo_f(hp1), e3 - bfhi_f(hp1));
        *(uint32_t*)(aoh + gr0 * INNER_ + col) = hp0;
        *(uint32_t*)(aol + gr0 * INNER_ + col) = lp0;
        *(uint32_t*)(aoh + (gr0 + 8) * INNER_ + col) = hp1;
        *(uint32_t*)(aol + (gr0 + 8) * INNER_ + col) = lp1;
    }
}

// ---------------------------------------------------------------------------
extern "C" void kernel_launch(void* const* d_in, const int* in_sizes, int n_in,
                              void* d_out, int out_size)
{
    const float* x   = (const float*)d_in[0];
    const float* Wq  = (const float*)d_in[1];
    const float* Wkv = (const float*)d_in[2];
    const float* Wo  = (const float*)d_in[3];
    const float* bo  = (const float*)d_in[4];
    float* out = (float*)d_out;

    __nv_bfloat16 *qkvh, *qkvl, *xh, *xl, *wth, *wtl, *woth, *wotl, *aoh, *aol;
    cudaGetSymbolAddress((void**)&qkvh, g_qkvh);
    cudaGetSymbolAddress((void**)&qkvl, g_qkvl);
    cudaGetSymbolAddress((void**)&xh,   g_xh);
    cudaGetSymbolAddress((void**)&xl,   g_xl);
    cudaGetSymbolAddress((void**)&wth,  g_wth);
    cudaGetSymbolAddress((void**)&wtl,  g_wtl);
    cudaGetSymbolAddress((void**)&woth, g_woth);
    cudaGetSymbolAddress((void**)&wotl, g_wotl);
    cudaGetSymbolAddress((void**)&aoh,  g_aoh);
    cudaGetSymbolAddress((void**)&aol,  g_aol);

    static bool attr_set = false;
    if (!attr_set) {
        cudaFuncSetAttribute(gemm_mma, cudaFuncAttributeMaxDynamicSharedMemorySize,
                             GEMM_SMEM);
        cudaFuncSetAttribute(flash_attn_mma, cudaFuncAttributeMaxDynamicSharedMemorySize,
                             AT_SMEM);
        attr_set = true;
    }

    const int n4x = ROWS_ * DIM_ / 4;
    conv_split<<<(n4x + 255) / 256, 256>>>(x, xh, xl, n4x);
    conv_wt<<<dim3(INNER_ / 32, DIM_ / 32), dim3(32, 8)>>>(Wq,  INNER_,     wth, wtl, 0);
    conv_wt<<<dim3(2 * INNER_ / 32, DIM_ / 32), dim3(32, 8)>>>(Wkv, 2 * INNER_, wth, wtl, 1024);
    conv_wt<<<dim3(DIM_ / 32, INNER_ / 32), dim3(32, 8)>>>(Wo,  DIM_,       woth, wotl, 0);

    // fused QKV projection -> split bf16 output
    gemm_mma<<<dim3(QKV_N / 128, ROWS_ / 128), 256, GEMM_SMEM>>>(
        xh, xl, wth, wtl, nullptr, nullptr, qkvh, qkvl, QKV_N, DIM_);

    // tensor-core flash attention -> split bf16 output
    flash_attn_mma<<<dim3(N_ / 128, H_, B_), 256, AT_SMEM>>>(qkvh, qkvl, aoh, aol);

    // out = ao @ Wo + bo (fp32 output)
    gemm_mma<<<dim3(DIM_ / 128, ROWS_ / 128), 256, GEMM_SMEM>>>(
        aoh, aol, woth, wotl, bo, out, nullptr, nullptr, DIM_, INNER_);
}

// round 7
// speedup vs baseline: 3.6888x; 1.2009x over previous
#include <cuda_runtime.h>
#include <cuda_bf16.h>
#include <cuda_fp16.h>
#include <math.h>
#include <cstdint>

// Problem constants
#define B_    4
#define N_    2048
#define DIM_  1024
#define H_    16
#define DH_   64
#define INNER_ 1024
#define ROWS_ (B_ * N_)   // 8192
#define QKV_N 3072        // fused [Q|K|V] columns

// ---------------------------------------------------------------------------
// Scratch (device globals — no cudaMalloc allowed)
// ---------------------------------------------------------------------------
__device__ __nv_bfloat16 g_qkvh[ROWS_ * QKV_N], g_qkvl[ROWS_ * QKV_N];
__device__ __half g_xh[ROWS_ * DIM_],  g_xl[ROWS_ * DIM_];
__device__ __half g_wt [QKV_N * DIM_];          // [n][k] fp16 single
__device__ __half g_wot[DIM_ * INNER_];         // [n][k] fp16 single
__device__ __half g_aoh[ROWS_ * INNER_], g_aol[ROWS_ * INNER_];

// ---------------------------------------------------------------------------
// helpers
// ---------------------------------------------------------------------------
__device__ __forceinline__ uint32_t smem_u32(const void* p) {
    uint32_t a;
    asm("{ .reg .u64 t; cvta.to.shared.u64 t, %1; cvt.u32.u64 %0, t; }"
        : "=r"(a) : "l"(p));
    return a;
}
#define CP16(dst, src) \
    asm volatile("cp.async.cg.shared.global [%0], [%1], 16;" :: "r"(dst), "l"(src))

__device__ __forceinline__ void ldsm_x4(uint32_t* r, uint32_t addr) {
    asm volatile("ldmatrix.sync.aligned.m8n8.x4.shared.b16 {%0,%1,%2,%3}, [%4];"
                 : "=r"(r[0]), "=r"(r[1]), "=r"(r[2]), "=r"(r[3]) : "r"(addr));
}
__device__ __forceinline__ void ldsm_x4t(uint32_t* r, uint32_t addr) {
    asm volatile("ldmatrix.sync.aligned.m8n8.x4.trans.shared.b16 {%0,%1,%2,%3}, [%4];"
                 : "=r"(r[0]), "=r"(r[1]), "=r"(r[2]), "=r"(r[3]) : "r"(addr));
}
__device__ __forceinline__ void mma_bf16(float* d, const uint32_t* a, const uint32_t* b) {
    asm volatile(
        "mma.sync.aligned.m16n8k16.row.col.f32.bf16.bf16.f32 "
        "{%0,%1,%2,%3}, {%4,%5,%6,%7}, {%8,%9}, {%0,%1,%2,%3};"
        : "+f"(d[0]), "+f"(d[1]), "+f"(d[2]), "+f"(d[3])
        : "r"(a[0]), "r"(a[1]), "r"(a[2]), "r"(a[3]), "r"(b[0]), "r"(b[1]));
}
__device__ __forceinline__ void mma_fp16(float* d, const uint32_t* a, const uint32_t* b) {
    asm volatile(
        "mma.sync.aligned.m16n8k16.row.col.f32.f16.f16.f32 "
        "{%0,%1,%2,%3}, {%4,%5,%6,%7}, {%8,%9}, {%0,%1,%2,%3};"
        : "+f"(d[0]), "+f"(d[1]), "+f"(d[2]), "+f"(d[3])
        : "r"(a[0]), "r"(a[1]), "r"(a[2]), "r"(a[3]), "r"(b[0]), "r"(b[1]));
}
// bf16 pack helpers (attention internals)
__device__ __forceinline__ uint32_t packbf(float lo, float hi) {
    __nv_bfloat162 t = __floats2bfloat162_rn(lo, hi);
    return *reinterpret_cast<uint32_t*>(&t);
}
__device__ __forceinline__ float bflo_f(uint32_t p) { return __uint_as_float(p << 16); }
__device__ __forceinline__ float bfhi_f(uint32_t p) { return __uint_as_float(p & 0xffff0000u); }
// fp16 pack helpers
__device__ __forceinline__ uint32_t packhf(float lo, float hi) {
    __half2 t = __floats2half2_rn(lo, hi);
    return *reinterpret_cast<uint32_t*>(&t);
}
__device__ __forceinline__ float hflo_f(uint32_t p) {
    return __half2float(__ushort_as_half((unsigned short)(p & 0xffffu)));
}
__device__ __forceinline__ float hfhi_f(uint32_t p) {
    return __half2float(__ushort_as_half((unsigned short)(p >> 16)));
}

// ---------------------------------------------------------------------------
// fp32 -> (fp16 hi, fp16 lo) element-wise split
// ---------------------------------------------------------------------------
__global__ void conv_split(const float* __restrict__ in,
                           __half* __restrict__ hi,
                           __half* __restrict__ lo, int n4)
{
    int i = blockIdx.x * blockDim.x + threadIdx.x;
    if (i >= n4) return;
    float4 v = ((const float4*)in)[i];
    __half h0 = __float2half_rn(v.x), h1 = __float2half_rn(v.y);
    __half h2 = __float2half_rn(v.z), h3 = __float2half_rn(v.w);
    __half l0 = __float2half_rn(v.x - __half2float(h0));
    __half l1 = __float2half_rn(v.y - __half2float(h1));
    __half l2 = __float2half_rn(v.z - __half2float(h2));
    __half l3 = __float2half_rn(v.w - __half2float(h3));
    __half2* H = (__half2*)hi;
    __half2* L = (__half2*)lo;
    H[i * 2]     = __halves2half2(h0, h1);
    H[i * 2 + 1] = __halves2half2(h2, h3);
    L[i * 2]     = __halves2half2(l0, l1);
    L[i * 2 + 1] = __halves2half2(l2, l3);
}

// ---------------------------------------------------------------------------
// W[k][n] fp32 -> Wt[n][k] fp16 single, rows [row_off, row_off+Nw), ld=1024
// ---------------------------------------------------------------------------
__global__ void conv_wt(const float* __restrict__ W, int Nw,
                        __half* __restrict__ outh, int row_off)
{
    __shared__ float t[32][33];
    const int bn = blockIdx.x * 32, bk = blockIdx.y * 32;
    const int tx = threadIdx.x, ty = threadIdx.y;
#pragma unroll
    for (int i = 0; i < 4; i++)
        t[ty + i * 8][tx] = W[(size_t)(bk + ty + i * 8) * Nw + bn + tx];
    __syncthreads();
#pragma unroll
    for (int i = 0; i < 4; i++) {
        float v = t[tx][ty + i * 8];
        size_t o = (size_t)(row_off + bn + ty + i * 8) * 1024 + bk + tx;
        outh[o] = __float2half_rn(v);
    }
}

// ---------------------------------------------------------------------------
// 2-pass fp16 GEMM: C[M,N] = (Ah+Al)[M,1024] * B[N,1024]^T (+bias)
// A split fp16 hi/lo; B single fp16 [n][k] (non-trans ldmatrix).
// Tile 128x128x64, 3-stage cp.async pipeline.
// If Ch != null: write split bf16 hi/lo instead of fp32.
// ---------------------------------------------------------------------------
#define BKg   64
#define LDS_  72                      // BK + 8 pad (halves); 144 B/row
#define TILE_B (128 * LDS_ * 2)       // 18432 B per matrix tile
#define STAGE_B (3 * TILE_B)          // Ah Al B = 55296
#define GEMM_SMEM (3 * STAGE_B)       // 165888 B

__global__ __launch_bounds__(256, 1)
void gemm_mma(const __half* __restrict__ Ah, const __half* __restrict__ Al,
              const __half* __restrict__ Bm,
              const float* __restrict__ bias, float* __restrict__ C,
              __nv_bfloat16* __restrict__ Ch, __nv_bfloat16* __restrict__ Cl,
              int ldC, int Kd)
{
    extern __shared__ char sm[];
    const uint32_t smb = smem_u32(sm);
    const int tid = threadIdx.x, wid = tid >> 5, lane = tid & 31;
    const int m0 = blockIdx.y * 128, n0 = blockIdx.x * 128;
    const int warp_m = (wid >> 2) * 64;    // 0 or 64
    const int warp_n = (wid & 3) * 32;     // 0,32,64,96

    float acc[4][4][4];
#pragma unroll
    for (int a = 0; a < 4; a++)
#pragma unroll
        for (int b = 0; b < 4; b++)
#pragma unroll
            for (int c = 0; c < 4; c++) acc[a][b][c] = 0.f;

    const int n_iters = Kd / BKg;

    auto issue_stage = [&](int buf, int k0) {
        const uint32_t sb = smb + buf * STAGE_B;
#pragma unroll
        for (int p = 0; p < 4; ++p) {
            const int idx = tid + p * 256;       // 0..1023
            const int r = idx >> 3;              // 0..127
            const int c = idx & 7;               // 0..7 (16B chunks)
            const uint32_t so = (uint32_t)r * (LDS_ * 2) + c * 16;
            const size_t goA = (size_t)(m0 + r) * 1024 + k0 + c * 8;
            const size_t goB = (size_t)(n0 + r) * 1024 + k0 + c * 8;
            CP16(sb + so,              (const char*)(Ah + goA));
            CP16(sb + TILE_B + so,     (const char*)(Al + goA));
            CP16(sb + 2 * TILE_B + so, (const char*)(Bm + goB));
        }
        asm volatile("cp.async.commit_group;" ::: "memory");
    };

    issue_stage(0, 0);
    issue_stage(1, BKg);

    const int a_row = warp_m + (lane & 15);
    const int a_col = (lane >> 4) << 3;
    const int b_row = warp_n + (lane & 7) + ((lane & 16) >> 1);
    const int b_col = (lane & 8);

    for (int it = 0; it < n_iters; ++it) {
        asm volatile("cp.async.wait_group 1;" ::: "memory");
        __syncthreads();
        if (it + 2 < n_iters) issue_stage((it + 2) % 3, (it + 2) * BKg);

        const uint32_t sb = smb + (it % 3) * STAGE_B;
        const uint32_t sAh = sb, sAl = sb + TILE_B;
        const uint32_t sB = sb + 2 * TILE_B;

#pragma unroll
        for (int ks = 0; ks < BKg / 16; ++ks) {
            const int koff = ks * 16;
            uint32_t afh[4][4], afl[4][4];
            uint32_t bf[4][2];
#pragma unroll
            for (int mf = 0; mf < 4; ++mf) {
                const uint32_t ao =
                    (uint32_t)(a_row + mf * 16) * (LDS_ * 2) + (a_col + koff) * 2;
                ldsm_x4(afh[mf], sAh + ao);
                ldsm_x4(afl[mf], sAl + ao);
            }
#pragma unroll
            for (int g = 0; g < 2; ++g) {
                const uint32_t bo =
                    (uint32_t)(b_row + g * 16) * (LDS_ * 2) + (b_col + koff) * 2;
                uint32_t th[4];
                ldsm_x4(th, sB + bo);        // NON-trans: B stored [n][k]
                bf[g * 2][0] = th[0]; bf[g * 2][1] = th[1];
                bf[g * 2 + 1][0] = th[2]; bf[g * 2 + 1][1] = th[3];
            }
#pragma unroll
            for (int mf = 0; mf < 4; ++mf)
#pragma unroll
                for (int nf = 0; nf < 4; ++nf) {
                    mma_fp16(acc[mf][nf], afh[mf], bf[nf]);
                    mma_fp16(acc[mf][nf], afl[mf], bf[nf]);
                }
        }
    }

    // ---- epilogue ----
    const int gid = lane >> 2, tig = lane & 3;
#pragma unroll
    for (int mf = 0; mf < 4; ++mf)
#pragma unroll
        for (int nf = 0; nf < 4; ++nf) {
            const int col = n0 + warp_n + nf * 8 + tig * 2;
            const int row0 = m0 + warp_m + mf * 16 + gid;
            if (Ch) {
                // split bf16 output (attention operands)
#pragma unroll
                for (int rr = 0; rr < 2; ++rr) {
                    const float e0 = acc[mf][nf][rr * 2], e1 = acc[mf][nf][rr * 2 + 1];
                    const uint32_t hp = packbf(e0, e1);
                    const uint32_t lp = packbf(e0 - bflo_f(hp), e1 - bfhi_f(hp));
                    const size_t off = (size_t)(row0 + rr * 8) * ldC + col;
                    *(uint32_t*)(Ch + off) = hp;
                    *(uint32_t*)(Cl + off) = lp;
                }
            } else {
                float2 v0 = make_float2(acc[mf][nf][0], acc[mf][nf][1]);
                float2 v1 = make_float2(acc[mf][nf][2], acc[mf][nf][3]);
                if (bias) {
                    const float b0 = bias[col], b1 = bias[col + 1];
                    v0.x += b0; v0.y += b1; v1.x += b0; v1.y += b1;
                }
                *(float2*)(C + (size_t)row0 * ldC + col) = v0;
                *(float2*)(C + (size_t)(row0 + 8) * ldC + col) = v1;
            }
        }
}

// ---------------------------------------------------------------------------
// Flash attention (causal) on tensor cores, split-bf16 3-pass (unchanged
// numerics), 3-stage KV pipeline, reversed ib for causal balance.
// Output: split fp16 hi/lo (operands of the final 2-pass GEMM).
// ---------------------------------------------------------------------------
#define AST   72                       // smem row stride in halves
#define QT_B  (128 * AST * 2)          // 18432
#define KT_B  (64 * AST * 2)           // 9216
#define KV_STAGE (4 * KT_B)            // 36864
#define AT_SMEM (2 * QT_B + 3 * KV_STAGE)   // 147456

__global__ __launch_bounds__(256, 1)
void flash_attn_mma(const __nv_bfloat16* __restrict__ qkvh,
                    const __nv_bfloat16* __restrict__ qkvl,
                    __half* __restrict__ aoh,
                    __half* __restrict__ aol)
{
    extern __shared__ char sm[];
    const uint32_t smb = smem_u32(sm);
    const uint32_t sQh = smb, sQl = smb + QT_B;
    const uint32_t kvb = smb + 2 * QT_B;

    const int tid = threadIdx.x, wid = tid >> 5, lane = tid & 31;
    const int gid = lane >> 2, tig = lane & 3;
    const int b = blockIdx.z, h = blockIdx.y;
    const int ib = gridDim.x - 1 - blockIdx.x;   // longest CTAs scheduled first

    const size_t rowQ0 = (size_t)b * N_ + ib * 128;
    const int colQ = h * DH_;
    const int colK = INNER_ + h * DH_;
    const int colV = 2 * INNER_ + h * DH_;

    // ---- Q loads (hi+lo), committed with first KV group ----
#pragma unroll
    for (int p = 0; p < 4; ++p) {
        const int idx = tid + p * 256;      // 0..1023
        const int r = idx >> 3, c = idx & 7;
        const uint32_t so = (uint32_t)r * (AST * 2) + c * 16;
        const size_t go = (rowQ0 + r) * QKV_N + colQ + c * 8;
        CP16(sQh + so, (const char*)(qkvh + go));
        CP16(sQl + so, (const char*)(qkvl + go));
    }

    auto issue_kv = [&](int jb, int buf) {
        const uint32_t sb = kvb + buf * KV_STAGE;
        const size_t rowK0 = (size_t)b * N_ + jb * 64;
#pragma unroll
        for (int p = 0; p < 2; ++p) {
            const int idx = tid + p * 256;  // 0..511
            const int r = idx >> 3, c = idx & 7;
            const uint32_t so = (uint32_t)r * (AST * 2) + c * 16;
            const size_t gk = (rowK0 + r) * QKV_N + colK + c * 8;
            const size_t gv = (rowK0 + r) * QKV_N + colV + c * 8;
            CP16(sb + so,            (const char*)(qkvh + gk));
            CP16(sb + KT_B + so,     (const char*)(qkvl + gk));
            CP16(sb + 2 * KT_B + so, (const char*)(qkvh + gv));
            CP16(sb + 3 * KT_B + so, (const char*)(qkvl + gv));
        }
        asm volatile("cp.async.commit_group;" ::: "memory");
    };

    issue_kv(0, 0);
    issue_kv(1, 1);

    float o[8][4];
#pragma unroll
    for (int i = 0; i < 8; i++)
#pragma unroll
        for (int j = 0; j < 4; j++) o[i][j] = 0.f;
    float m0 = -INFINITY, m1 = -INFINITY, l0 = 0.f, l1 = 0.f;

    // fragment addressing
    const int a_row = wid * 16 + (lane & 15);
    const int a_col = (lane >> 4) << 3;
    const int bk_row = (lane & 7) + ((lane & 16) >> 1);   // K b-frag (non-trans)
    const int bk_col = (lane & 8);
    const int v_row = (lane & 15);                        // V b-frag (trans)
    const int v_col = (lane >> 4) << 3;

    const int row0g = ib * 128 + wid * 16 + gid;          // global q rows
    const int row1g = row0g + 8;
    const int ntiles = 2 * ib + 2;

    for (int jb = 0; jb < ntiles; ++jb) {
        asm volatile("cp.async.wait_group 1;" ::: "memory");
        __syncthreads();
        if (jb + 2 < ntiles) issue_kv(jb + 2, (jb + 2) % 3);

        const uint32_t sb = kvb + (jb % 3) * KV_STAGE;
        const uint32_t sKh = sb, sKl = sb + KT_B;
        const uint32_t sVh = sb + 2 * KT_B, sVl = sb + 3 * KT_B;

        // ---- S = Q K^T (split bf16, 3 passes) ----
        float s[8][4];
#pragma unroll
        for (int i = 0; i < 8; i++)
#pragma unroll
            for (int j = 0; j < 4; j++) s[i][j] = 0.f;

#pragma unroll
        for (int ks = 0; ks < 4; ++ks) {
            uint32_t qh[4], ql[4];
            const uint32_t ao = (uint32_t)a_row * (AST * 2) + (a_col + ks * 16) * 2;
            ldsm_x4(qh, sQh + ao);
            ldsm_x4(ql, sQl + ao);
#pragma unroll
            for (int g = 0; g < 4; ++g) {
                const uint32_t bo =
                    (uint32_t)(g * 16 + bk_row) * (AST * 2) + (ks * 16 + bk_col) * 2;
                uint32_t kh[4], kl[4];
                ldsm_x4(kh, sKh + bo);
                ldsm_x4(kl, sKl + bo);
                mma_bf16(s[g * 2],     qh, kh);
                mma_bf16(s[g * 2],     qh, kl);
                mma_bf16(s[g * 2],     ql, kh);
                mma_bf16(s[g * 2 + 1], qh, kh + 2);
                mma_bf16(s[g * 2 + 1], qh, kl + 2);
                mma_bf16(s[g * 2 + 1], ql, kh + 2);
            }
        }

        // ---- scale + causal mask ----
#pragma unroll
        for (int nf = 0; nf < 8; ++nf)
#pragma unroll
            for (int e = 0; e < 4; ++e) s[nf][e] *= 0.125f;
        if (jb >= 2 * ib) {
#pragma unroll
            for (int nf = 0; nf < 8; ++nf) {
                const int col = jb * 64 + nf * 8 + tig * 2;
                if (col     > row0g) s[nf][0] = -INFINITY;
                if (col + 1 > row0g) s[nf][1] = -INFINITY;
                if (col     > row1g) s[nf][2] = -INFINITY;
                if (col + 1 > row1g) s[nf][3] = -INFINITY;
            }
        }

        // ---- online softmax ----
        float mx0 = -INFINITY, mx1 = -INFINITY;
#pragma unroll
        for (int nf = 0; nf < 8; ++nf) {
            mx0 = fmaxf(mx0, fmaxf(s[nf][0], s[nf][1]));
            mx1 = fmaxf(mx1, fmaxf(s[nf][2], s[nf][3]));
        }
        mx0 = fmaxf(mx0, __shfl_xor_sync(0xffffffffu, mx0, 1));
        mx0 = fmaxf(mx0, __shfl_xor_sync(0xffffffffu, mx0, 2));
        mx1 = fmaxf(mx1, __shfl_xor_sync(0xffffffffu, mx1, 1));
        mx1 = fmaxf(mx1, __shfl_xor_sync(0xffffffffu, mx1, 2));
        const float nm0 = fmaxf(m0, mx0), nm1 = fmaxf(m1, mx1);
        const float fac0 = __expf(m0 - nm0), fac1 = __expf(m1 - nm1);
        m0 = nm0; m1 = nm1;

        float sum0 = 0.f, sum1 = 0.f;
#pragma unroll
        for (int nf = 0; nf < 8; ++nf) {
            s[nf][0] = __expf(s[nf][0] - nm0);
            s[nf][1] = __expf(s[nf][1] - nm0);
            s[nf][2] = __expf(s[nf][2] - nm1);
            s[nf][3] = __expf(s[nf][3] - nm1);
            sum0 += s[nf][0] + s[nf][1];
            sum1 += s[nf][2] + s[nf][3];
        }
        sum0 += __shfl_xor_sync(0xffffffffu, sum0, 1);
        sum0 += __shfl_xor_sync(0xffffffffu, sum0, 2);
        sum1 += __shfl_xor_sync(0xffffffffu, sum1, 1);
        sum1 += __shfl_xor_sync(0xffffffffu, sum1, 2);
        l0 = l0 * fac0 + sum0;
        l1 = l1 * fac1 + sum1;
#pragma unroll
        for (int nf = 0; nf < 8; ++nf) {
            o[nf][0] *= fac0; o[nf][1] *= fac0;
            o[nf][2] *= fac1; o[nf][3] *= fac1;
        }

        // ---- O += P V (split bf16, 3 passes); P repacked C-frag -> A-frag ----
#pragma unroll
        for (int kb = 0; kb < 4; ++kb) {
            uint32_t ph[4], pl[4];
#pragma unroll
            for (int half = 0; half < 2; ++half) {
                const float* pp = s[2 * kb + half];
                const uint32_t h01 = packbf(pp[0], pp[1]);
                const uint32_t h23 = packbf(pp[2], pp[3]);
                const uint32_t l01 = packbf(pp[0] - bflo_f(h01), pp[1] - bfhi_f(h01));
                const uint32_t l23 = packbf(pp[2] - bflo_f(h23), pp[3] - bfhi_f(h23));
                ph[half * 2] = h01; ph[half * 2 + 1] = h23;
                pl[half * 2] = l01; pl[half * 2 + 1] = l23;
            }
#pragma unroll
            for (int g = 0; g < 4; ++g) {
                const uint32_t bo =
                    (uint32_t)(kb * 16 + v_row) * (AST * 2) + (g * 16 + v_col) * 2;
                uint32_t vh[4], vl[4];
                ldsm_x4t(vh, sVh + bo);
                ldsm_x4t(vl, sVl + bo);
                mma_bf16(o[g * 2],     ph, vh);
                mma_bf16(o[g * 2],     ph, vl);
                mma_bf16(o[g * 2],     pl, vh);
                mma_bf16(o[g * 2 + 1], ph, vh + 2);
                mma_bf16(o[g * 2 + 1], ph, vl + 2);
                mma_bf16(o[g * 2 + 1], pl, vh + 2);
            }
        }
    }

    // ---- epilogue: normalize, split to fp16 hi/lo, store ----
    const float inv0 = 1.f / l0, inv1 = 1.f / l1;
    const size_t gr0 = (size_t)b * N_ + ib * 128 + wid * 16 + gid;
#pragma unroll
    for (int nf = 0; nf < 8; ++nf) {
        const int col = h * DH_ + nf * 8 + tig * 2;
        const float e0 = o[nf][0] * inv0, e1 = o[nf][1] * inv0;
        const float e2 = o[nf][2] * inv1, e3 = o[nf][3] * inv1;
        const uint32_t hp0 = packhf(e0, e1);
        const uint32_t lp0 = packhf(e0 - hflo_f(hp0), e1 - hfhi_f(hp0));
        const uint32_t hp1 = packhf(e2, e3);
        const uint32_t lp1 = packhf(e2 - hflo_f(hp1), e3 - hfhi_f(hp1));
        *(uint32_t*)(aoh + gr0 * INNER_ + col) = hp0;
        *(uint32_t*)(aol + gr0 * INNER_ + col) = lp0;
        *(uint32_t*)(aoh + (gr0 + 8) * INNER_ + col) = hp1;
        *(uint32_t*)(aol + (gr0 + 8) * INNER_ + col) = lp1;
    }
}

// ---------------------------------------------------------------------------
extern "C" void kernel_launch(void* const* d_in, const int* in_sizes, int n_in,
                              void* d_out, int out_size)
{
    const float* x   = (const float*)d_in[0];
    const float* Wq  = (const float*)d_in[1];
    const float* Wkv = (const float*)d_in[2];
    const float* Wo  = (const float*)d_in[3];
    const float* bo  = (const float*)d_in[4];
    float* out = (float*)d_out;

    __nv_bfloat16 *qkvh, *qkvl;
    __half *xh, *xl, *wt, *wot, *aoh, *aol;
    cudaGetSymbolAddress((void**)&qkvh, g_qkvh);
    cudaGetSymbolAddress((void**)&qkvl, g_qkvl);
    cudaGetSymbolAddress((void**)&xh,   g_xh);
    cudaGetSymbolAddress((void**)&xl,   g_xl);
    cudaGetSymbolAddress((void**)&wt,   g_wt);
    cudaGetSymbolAddress((void**)&wot,  g_wot);
    cudaGetSymbolAddress((void**)&aoh,  g_aoh);
    cudaGetSymbolAddress((void**)&aol,  g_aol);

    static bool attr_set = false;
    if (!attr_set) {
        cudaFuncSetAttribute(gemm_mma, cudaFuncAttributeMaxDynamicSharedMemorySize,
                             GEMM_SMEM);
        cudaFuncSetAttribute(flash_attn_mma, cudaFuncAttributeMaxDynamicSharedMemorySize,
                             AT_SMEM);
        attr_set = true;
    }

    const int n4x = ROWS_ * DIM_ / 4;
    conv_split<<<(n4x + 255) / 256, 256>>>(x, xh, xl, n4x);
    conv_wt<<<dim3(INNER_ / 32, DIM_ / 32), dim3(32, 8)>>>(Wq,  INNER_,     wt, 0);
    conv_wt<<<dim3(2 * INNER_ / 32, DIM_ / 32), dim3(32, 8)>>>(Wkv, 2 * INNER_, wt, 1024);
    conv_wt<<<dim3(DIM_ / 32, INNER_ / 32), dim3(32, 8)>>>(Wo,  DIM_,       wot, 0);

    // fused QKV projection (2-pass fp16) -> split bf16 output
    gemm_mma<<<dim3(QKV_N / 128, ROWS_ / 128), 256, GEMM_SMEM>>>(
        xh, xl, wt, nullptr, nullptr, qkvh, qkvl, QKV_N, DIM_);

    // tensor-core flash attention (3-pass bf16) -> split fp16 output
    flash_attn_mma<<<dim3(N_ / 128, H_, B_), 256, AT_SMEM>>>(qkvh, qkvl, aoh, aol);

    // out = ao @ Wo + bo (2-pass fp16, fp32 output)
    gemm_mma<<<dim3(DIM_ / 128, ROWS_ / 128), 256, GEMM_SMEM>>>(
        aoh, aol, wot, bo, out, nullptr, nullptr, DIM_, INNER_);
}

// round 8
// speedup vs baseline: 4.1618x; 1.1282x over previous
#include <cuda_runtime.h>
#include <cuda_bf16.h>
#include <cuda_fp16.h>
#include <math.h>
#include <cstdint>

// Problem constants
#define B_    4
#define N_    2048
#define DIM_  1024
#define H_    16
#define DH_   64
#define INNER_ 1024
#define ROWS_ (B_ * N_)   // 8192
#define QKV_N 3072        // fused [Q|K|V] columns

// ---------------------------------------------------------------------------
// Scratch (device globals — no cudaMalloc allowed)
// ---------------------------------------------------------------------------
__device__ __half g_qkvh[ROWS_ * QKV_N], g_qkvl[ROWS_ * QKV_N];
__device__ __half g_xh[ROWS_ * DIM_],  g_xl[ROWS_ * DIM_];
__device__ __half g_wt [QKV_N * DIM_];          // [n][k] fp16 single
__device__ __half g_wot[DIM_ * INNER_];         // [n][k] fp16 single
__device__ __half g_aoh[ROWS_ * INNER_], g_aol[ROWS_ * INNER_];

// ---------------------------------------------------------------------------
// helpers
// ---------------------------------------------------------------------------
__device__ __forceinline__ uint32_t smem_u32(const void* p) {
    uint32_t a;
    asm("{ .reg .u64 t; cvta.to.shared.u64 t, %1; cvt.u32.u64 %0, t; }"
        : "=r"(a) : "l"(p));
    return a;
}
#define CP16(dst, src) \
    asm volatile("cp.async.cg.shared.global [%0], [%1], 16;" :: "r"(dst), "l"(src))

__device__ __forceinline__ void ldsm_x4(uint32_t* r, uint32_t addr) {
    asm volatile("ldmatrix.sync.aligned.m8n8.x4.shared.b16 {%0,%1,%2,%3}, [%4];"
                 : "=r"(r[0]), "=r"(r[1]), "=r"(r[2]), "=r"(r[3]) : "r"(addr));
}
__device__ __forceinline__ void ldsm_x4t(uint32_t* r, uint32_t addr) {
    asm volatile("ldmatrix.sync.aligned.m8n8.x4.trans.shared.b16 {%0,%1,%2,%3}, [%4];"
                 : "=r"(r[0]), "=r"(r[1]), "=r"(r[2]), "=r"(r[3]) : "r"(addr));
}
__device__ __forceinline__ void mma_fp16(float* d, const uint32_t* a, const uint32_t* b) {
    asm volatile(
        "mma.sync.aligned.m16n8k16.row.col.f32.f16.f16.f32 "
        "{%0,%1,%2,%3}, {%4,%5,%6,%7}, {%8,%9}, {%0,%1,%2,%3};"
        : "+f"(d[0]), "+f"(d[1]), "+f"(d[2]), "+f"(d[3])
        : "r"(a[0]), "r"(a[1]), "r"(a[2]), "r"(a[3]), "r"(b[0]), "r"(b[1]));
}
// fp16 pack helpers
__device__ __forceinline__ uint32_t packhf(float lo, float hi) {
    __half2 t = __floats2half2_rn(lo, hi);
    return *reinterpret_cast<uint32_t*>(&t);
}
__device__ __forceinline__ float hflo_f(uint32_t p) {
    return __half2float(__ushort_as_half((unsigned short)(p & 0xffffu)));
}
__device__ __forceinline__ float hfhi_f(uint32_t p) {
    return __half2float(__ushort_as_half((unsigned short)(p >> 16)));
}

// ---------------------------------------------------------------------------
// fp32 -> (fp16 hi, fp16 lo) element-wise split
// ---------------------------------------------------------------------------
__global__ void conv_split(const float* __restrict__ in,
                           __half* __restrict__ hi,
                           __half* __restrict__ lo, int n4)
{
    int i = blockIdx.x * blockDim.x + threadIdx.x;
    if (i >= n4) return;
    float4 v = ((const float4*)in)[i];
    __half h0 = __float2half_rn(v.x), h1 = __float2half_rn(v.y);
    __half h2 = __float2half_rn(v.z), h3 = __float2half_rn(v.w);
    __half l0 = __float2half_rn(v.x - __half2float(h0));
    __half l1 = __float2half_rn(v.y - __half2float(h1));
    __half l2 = __float2half_rn(v.z - __half2float(h2));
    __half l3 = __float2half_rn(v.w - __half2float(h3));
    __half2* H = (__half2*)hi;
    __half2* L = (__half2*)lo;
    H[i * 2]     = __halves2half2(h0, h1);
    H[i * 2 + 1] = __halves2half2(h2, h3);
    L[i * 2]     = __halves2half2(l0, l1);
    L[i * 2 + 1] = __halves2half2(l2, l3);
}

// ---------------------------------------------------------------------------
// W[k][n] fp32 -> Wt[n][k] fp16 single, rows [row_off, row_off+Nw), ld=1024
// ---------------------------------------------------------------------------
__global__ void conv_wt(const float* __restrict__ W, int Nw,
                        __half* __restrict__ outh, int row_off)
{
    __shared__ float t[32][33];
    const int bn = blockIdx.x * 32, bk = blockIdx.y * 32;
    const int tx = threadIdx.x, ty = threadIdx.y;
#pragma unroll
    for (int i = 0; i < 4; i++)
        t[ty + i * 8][tx] = W[(size_t)(bk + ty + i * 8) * Nw + bn + tx];
    __syncthreads();
#pragma unroll
    for (int i = 0; i < 4; i++) {
        float v = t[tx][ty + i * 8];
        size_t o = (size_t)(row_off + bn + ty + i * 8) * 1024 + bk + tx;
        outh[o] = __float2half_rn(v);
    }
}

// ---------------------------------------------------------------------------
// 2-pass fp16 GEMM: C[M,N] = (Ah+Al)[M,1024] * B[N,1024]^T (+bias)
// A split fp16 hi/lo; B single fp16 [n][k] (non-trans ldmatrix).
// Tile 128x128x64, 3-stage cp.async pipeline.
// If Ch != null: write split fp16 hi/lo instead of fp32.
// ---------------------------------------------------------------------------
#define BKg   64
#define LDS_  72                      // BK + 8 pad (halves); 144 B/row
#define TILE_B (128 * LDS_ * 2)       // 18432 B per matrix tile
#define STAGE_B (3 * TILE_B)          // Ah Al B = 55296
#define GEMM_SMEM (3 * STAGE_B)       // 165888 B

__global__ __launch_bounds__(256, 1)
void gemm_mma(const __half* __restrict__ Ah, const __half* __restrict__ Al,
              const __half* __restrict__ Bm,
              const float* __restrict__ bias, float* __restrict__ C,
              __half* __restrict__ Ch, __half* __restrict__ Cl,
              int ldC, int Kd)
{
    extern __shared__ char sm[];
    const uint32_t smb = smem_u32(sm);
    const int tid = threadIdx.x, wid = tid >> 5, lane = tid & 31;
    const int m0 = blockIdx.y * 128, n0 = blockIdx.x * 128;
    const int warp_m = (wid >> 2) * 64;    // 0 or 64
    const int warp_n = (wid & 3) * 32;     // 0,32,64,96

    float acc[4][4][4];
#pragma unroll
    for (int a = 0; a < 4; a++)
#pragma unroll
        for (int b = 0; b < 4; b++)
#pragma unroll
            for (int c = 0; c < 4; c++) acc[a][b][c] = 0.f;

    const int n_iters = Kd / BKg;

    auto issue_stage = [&](int buf, int k0) {
        const uint32_t sb = smb + buf * STAGE_B;
#pragma unroll
        for (int p = 0; p < 4; ++p) {
            const int idx = tid + p * 256;       // 0..1023
            const int r = idx >> 3;              // 0..127
            const int c = idx & 7;               // 0..7 (16B chunks)
            const uint32_t so = (uint32_t)r * (LDS_ * 2) + c * 16;
            const size_t goA = (size_t)(m0 + r) * 1024 + k0 + c * 8;
            const size_t goB = (size_t)(n0 + r) * 1024 + k0 + c * 8;
            CP16(sb + so,              (const char*)(Ah + goA));
            CP16(sb + TILE_B + so,     (const char*)(Al + goA));
            CP16(sb + 2 * TILE_B + so, (const char*)(Bm + goB));
        }
        asm volatile("cp.async.commit_group;" ::: "memory");
    };

    issue_stage(0, 0);
    issue_stage(1, BKg);

    const int a_row = warp_m + (lane & 15);
    const int a_col = (lane >> 4) << 3;
    const int b_row = warp_n + (lane & 7) + ((lane & 16) >> 1);
    const int b_col = (lane & 8);

    for (int it = 0; it < n_iters; ++it) {
        asm volatile("cp.async.wait_group 1;" ::: "memory");
        __syncthreads();
        if (it + 2 < n_iters) issue_stage((it + 2) % 3, (it + 2) * BKg);

        const uint32_t sb = smb + (it % 3) * STAGE_B;
        const uint32_t sAh = sb, sAl = sb + TILE_B;
        const uint32_t sB = sb + 2 * TILE_B;

#pragma unroll
        for (int ks = 0; ks < BKg / 16; ++ks) {
            const int koff = ks * 16;
            uint32_t afh[4][4], afl[4][4];
            uint32_t bf[4][2];
#pragma unroll
            for (int mf = 0; mf < 4; ++mf) {
                const uint32_t ao =
                    (uint32_t)(a_row + mf * 16) * (LDS_ * 2) + (a_col + koff) * 2;
                ldsm_x4(afh[mf], sAh + ao);
                ldsm_x4(afl[mf], sAl + ao);
            }
#pragma unroll
            for (int g = 0; g < 2; ++g) {
                const uint32_t bo =
                    (uint32_t)(b_row + g * 16) * (LDS_ * 2) + (b_col + koff) * 2;
                uint32_t th[4];
                ldsm_x4(th, sB + bo);        // NON-trans: B stored [n][k]
                bf[g * 2][0] = th[0]; bf[g * 2][1] = th[1];
                bf[g * 2 + 1][0] = th[2]; bf[g * 2 + 1][1] = th[3];
            }
#pragma unroll
            for (int mf = 0; mf < 4; ++mf)
#pragma unroll
                for (int nf = 0; nf < 4; ++nf) {
                    mma_fp16(acc[mf][nf], afh[mf], bf[nf]);
                    mma_fp16(acc[mf][nf], afl[mf], bf[nf]);
                }
        }
    }

    // ---- epilogue ----
    const int gid = lane >> 2, tig = lane & 3;
#pragma unroll
    for (int mf = 0; mf < 4; ++mf)
#pragma unroll
        for (int nf = 0; nf < 4; ++nf) {
            const int col = n0 + warp_n + nf * 8 + tig * 2;
            const int row0 = m0 + warp_m + mf * 16 + gid;
            if (Ch) {
                // split fp16 output (attention operands)
#pragma unroll
                for (int rr = 0; rr < 2; ++rr) {
                    const float e0 = acc[mf][nf][rr * 2], e1 = acc[mf][nf][rr * 2 + 1];
                    const uint32_t hp = packhf(e0, e1);
                    const uint32_t lp = packhf(e0 - hflo_f(hp), e1 - hfhi_f(hp));
                    const size_t off = (size_t)(row0 + rr * 8) * ldC + col;
                    *(uint32_t*)(Ch + off) = hp;
                    *(uint32_t*)(Cl + off) = lp;
                }
            } else {
                float2 v0 = make_float2(acc[mf][nf][0], acc[mf][nf][1]);
                float2 v1 = make_float2(acc[mf][nf][2], acc[mf][nf][3]);
                if (bias) {
                    const float b0 = bias[col], b1 = bias[col + 1];
                    v0.x += b0; v0.y += b1; v1.x += b0; v1.y += b1;
                }
                *(float2*)(C + (size_t)row0 * ldC + col) = v0;
                *(float2*)(C + (size_t)(row0 + 8) * ldC + col) = v1;
            }
        }
}

// ---------------------------------------------------------------------------
// Flash attention (causal), fp16 tensor cores, 2-pass everywhere:
//   QK^T = (Qh+Ql) * Kh ;  PV = (Ph+Pl) * Vh   (K,V single fp16)
// CTA = 128 q rows of one (b,h); 8 warps x 16 rows. Key tiles of 64.
// 3-stage KV pipeline (Kh,Vh per stage), reversed ib for causal balance.
// Output: split fp16 hi/lo.
// ---------------------------------------------------------------------------
#define AST   72                       // smem row stride in halves
#define QT_B  (128 * AST * 2)          // 18432
#define KT_B  (64 * AST * 2)           // 9216
#define KV_STAGE (2 * KT_B)            // 18432 (Kh, Vh)
#define AT_SMEM (2 * QT_B + 3 * KV_STAGE)   // 92160

__global__ __launch_bounds__(256, 1)
void flash_attn_mma(const __half* __restrict__ qkvh,
                    const __half* __restrict__ qkvl,
                    __half* __restrict__ aoh,
                    __half* __restrict__ aol)
{
    extern __shared__ char sm[];
    const uint32_t smb = smem_u32(sm);
    const uint32_t sQh = smb, sQl = smb + QT_B;
    const uint32_t kvb = smb + 2 * QT_B;

    const int tid = threadIdx.x, wid = tid >> 5, lane = tid & 31;
    const int gid = lane >> 2, tig = lane & 3;
    const int b = blockIdx.z, h = blockIdx.y;
    const int ib = gridDim.x - 1 - blockIdx.x;   // longest CTAs scheduled first

    const size_t rowQ0 = (size_t)b * N_ + ib * 128;
    const int colQ = h * DH_;
    const int colK = INNER_ + h * DH_;
    const int colV = 2 * INNER_ + h * DH_;

    // ---- Q loads (hi+lo), committed with first KV group ----
#pragma unroll
    for (int p = 0; p < 4; ++p) {
        const int idx = tid + p * 256;      // 0..1023
        const int r = idx >> 3, c = idx & 7;
        const uint32_t so = (uint32_t)r * (AST * 2) + c * 16;
        const size_t go = (rowQ0 + r) * QKV_N + colQ + c * 8;
        CP16(sQh + so, (const char*)(qkvh + go));
        CP16(sQl + so, (const char*)(qkvl + go));
    }

    auto issue_kv = [&](int jb, int buf) {
        const uint32_t sb = kvb + buf * KV_STAGE;
        const size_t rowK0 = (size_t)b * N_ + jb * 64;
#pragma unroll
        for (int p = 0; p < 2; ++p) {
            const int idx = tid + p * 256;  // 0..511
            const int r = idx >> 3, c = idx & 7;
            const uint32_t so = (uint32_t)r * (AST * 2) + c * 16;
            const size_t gk = (rowK0 + r) * QKV_N + colK + c * 8;
            const size_t gv = (rowK0 + r) * QKV_N + colV + c * 8;
            CP16(sb + so,        (const char*)(qkvh + gk));   // Kh
            CP16(sb + KT_B + so, (const char*)(qkvh + gv));   // Vh
        }
        asm volatile("cp.async.commit_group;" ::: "memory");
    };

    issue_kv(0, 0);
    issue_kv(1, 1);

    float o[8][4];
#pragma unroll
    for (int i = 0; i < 8; i++)
#pragma unroll
        for (int j = 0; j < 4; j++) o[i][j] = 0.f;
    float m0 = -INFINITY, m1 = -INFINITY, l0 = 0.f, l1 = 0.f;

    // fragment addressing
    const int a_row = wid * 16 + (lane & 15);
    const int a_col = (lane >> 4) << 3;
    const int bk_row = (lane & 7) + ((lane & 16) >> 1);   // K b-frag (non-trans)
    const int bk_col = (lane & 8);
    const int v_row = (lane & 15);                        // V b-frag (trans)
    const int v_col = (lane >> 4) << 3;

    const int row0g = ib * 128 + wid * 16 + gid;          // global q rows
    const int row1g = row0g + 8;
    const int ntiles = 2 * ib + 2;

    for (int jb = 0; jb < ntiles; ++jb) {
        asm volatile("cp.async.wait_group 1;" ::: "memory");
        __syncthreads();
        if (jb + 2 < ntiles) issue_kv(jb + 2, (jb + 2) % 3);

        const uint32_t sb = kvb + (jb % 3) * KV_STAGE;
        const uint32_t sKh = sb, sVh = sb + KT_B;

        // ---- S = Q K^T (2 passes: Qh*K + Ql*K) ----
        float s[8][4];
#pragma unroll
        for (int i = 0; i < 8; i++)
#pragma unroll
            for (int j = 0; j < 4; j++) s[i][j] = 0.f;

#pragma unroll
        for (int ks = 0; ks < 4; ++ks) {
            uint32_t qh[4], ql[4];
            const uint32_t ao = (uint32_t)a_row * (AST * 2) + (a_col + ks * 16) * 2;
            ldsm_x4(qh, sQh + ao);
            ldsm_x4(ql, sQl + ao);
#pragma unroll
            for (int g = 0; g < 4; ++g) {
                const uint32_t bo =
                    (uint32_t)(g * 16 + bk_row) * (AST * 2) + (ks * 16 + bk_col) * 2;
                uint32_t kh[4];
                ldsm_x4(kh, sKh + bo);
                mma_fp16(s[g * 2],     qh, kh);
                mma_fp16(s[g * 2],     ql, kh);
                mma_fp16(s[g * 2 + 1], qh, kh + 2);
                mma_fp16(s[g * 2 + 1], ql, kh + 2);
            }
        }

        // ---- scale + causal mask ----
#pragma unroll
        for (int nf = 0; nf < 8; ++nf)
#pragma unroll
            for (int e = 0; e < 4; ++e) s[nf][e] *= 0.125f;
        if (jb >= 2 * ib) {
#pragma unroll
            for (int nf = 0; nf < 8; ++nf) {
                const int col = jb * 64 + nf * 8 + tig * 2;
                if (col     > row0g) s[nf][0] = -INFINITY;
                if (col + 1 > row0g) s[nf][1] = -INFINITY;
                if (col     > row1g) s[nf][2] = -INFINITY;
                if (col + 1 > row1g) s[nf][3] = -INFINITY;
            }
        }

        // ---- online softmax ----
        float mx0 = -INFINITY, mx1 = -INFINITY;
#pragma unroll
        for (int nf = 0; nf < 8; ++nf) {
            mx0 = fmaxf(mx0, fmaxf(s[nf][0], s[nf][1]));
            mx1 = fmaxf(mx1, fmaxf(s[nf][2], s[nf][3]));
        }
        mx0 = fmaxf(mx0, __shfl_xor_sync(0xffffffffu, mx0, 1));
        mx0 = fmaxf(mx0, __shfl_xor_sync(0xffffffffu, mx0, 2));
        mx1 = fmaxf(mx1, __shfl_xor_sync(0xffffffffu, mx1, 1));
        mx1 = fmaxf(mx1, __shfl_xor_sync(0xffffffffu, mx1, 2));
        const float nm0 = fmaxf(m0, mx0), nm1 = fmaxf(m1, mx1);
        const float fac0 = __expf(m0 - nm0), fac1 = __expf(m1 - nm1);
        m0 = nm0; m1 = nm1;

        float sum0 = 0.f, sum1 = 0.f;
#pragma unroll
        for (int nf = 0; nf < 8; ++nf) {
            s[nf][0] = __expf(s[nf][0] - nm0);
            s[nf][1] = __expf(s[nf][1] - nm0);
            s[nf][2] = __expf(s[nf][2] - nm1);
            s[nf][3] = __expf(s[nf][3] - nm1);
            sum0 += s[nf][0] + s[nf][1];
            sum1 += s[nf][2] + s[nf][3];
        }
        sum0 += __shfl_xor_sync(0xffffffffu, sum0, 1);
        sum0 += __shfl_xor_sync(0xffffffffu, sum0, 2);
        sum1 += __shfl_xor_sync(0xffffffffu, sum1, 1);
        sum1 += __shfl_xor_sync(0xffffffffu, sum1, 2);
        l0 = l0 * fac0 + sum0;
        l1 = l1 * fac1 + sum1;
#pragma unroll
        for (int nf = 0; nf < 8; ++nf) {
            o[nf][0] *= fac0; o[nf][1] *= fac0;
            o[nf][2] *= fac1; o[nf][3] *= fac1;
        }

        // ---- O += P V (2 passes: Ph*V + Pl*V); P repacked C->A frag fp16 ----
#pragma unroll
        for (int kb = 0; kb < 4; ++kb) {
            uint32_t ph[4], pl[4];
#pragma unroll
            for (int half = 0; half < 2; ++half) {
                const float* pp = s[2 * kb + half];
                const uint32_t h01 = packhf(pp[0], pp[1]);
                const uint32_t h23 = packhf(pp[2], pp[3]);
                const uint32_t l01 = packhf(pp[0] - hflo_f(h01), pp[1] - hfhi_f(h01));
                const uint32_t l23 = packhf(pp[2] - hflo_f(h23), pp[3] - hfhi_f(h23));
                ph[half * 2] = h01; ph[half * 2 + 1] = h23;
                pl[half * 2] = l01; pl[half * 2 + 1] = l23;
            }
#pragma unroll
            for (int g = 0; g < 4; ++g) {
                const uint32_t bo =
                    (uint32_t)(kb * 16 + v_row) * (AST * 2) + (g * 16 + v_col) * 2;
                uint32_t vh[4];
                ldsm_x4t(vh, sVh + bo);
                mma_fp16(o[g * 2],     ph, vh);
                mma_fp16(o[g * 2],     pl, vh);
                mma_fp16(o[g * 2 + 1], ph, vh + 2);
                mma_fp16(o[g * 2 + 1], pl, vh + 2);
            }
        }
    }

    // ---- epilogue: normalize, split to fp16 hi/lo, store ----
    const float inv0 = 1.f / l0, inv1 = 1.f / l1;
    const size_t gr0 = (size_t)b * N_ + ib * 128 + wid * 16 + gid;
#pragma unroll
    for (int nf = 0; nf < 8; ++nf) {
        const int col = h * DH_ + nf * 8 + tig * 2;
        const float e0 = o[nf][0] * inv0, e1 = o[nf][1] * inv0;
        const float e2 = o[nf][2] * inv1, e3 = o[nf][3] * inv1;
        const uint32_t hp0 = packhf(e0, e1);
        const uint32_t lp0 = packhf(e0 - hflo_f(hp0), e1 - hfhi_f(hp0));
        const uint32_t hp1 = packhf(e2, e3);
        const uint32_t lp1 = packhf(e2 - hflo_f(hp1), e3 - hfhi_f(hp1));
        *(uint32_t*)(aoh + gr0 * INNER_ + col) = hp0;
        *(uint32_t*)(aol + gr0 * INNER_ + col) = lp0;
        *(uint32_t*)(aoh + (gr0 + 8) * INNER_ + col) = hp1;
        *(uint32_t*)(aol + (gr0 + 8) * INNER_ + col) = lp1;
    }
}

// ---------------------------------------------------------------------------
extern "C" void kernel_launch(void* const* d_in, const int* in_sizes, int n_in,
                              void* d_out, int out_size)
{
    const float* x   = (const float*)d_in[0];
    const float* Wq  = (const float*)d_in[1];
    const float* Wkv = (const float*)d_in[2];
    const float* Wo  = (const float*)d_in[3];
    const float* bo  = (const float*)d_in[4];
    float* out = (float*)d_out;

    __half *qkvh, *qkvl, *xh, *xl, *wt, *wot, *aoh, *aol;
    cudaGetSymbolAddress((void**)&qkvh, g_qkvh);
    cudaGetSymbolAddress((void**)&qkvl, g_qkvl);
    cudaGetSymbolAddress((void**)&xh,   g_xh);
    cudaGetSymbolAddress((void**)&xl,   g_xl);
    cudaGetSymbolAddress((void**)&wt,   g_wt);
    cudaGetSymbolAddress((void**)&wot,  g_wot);
    cudaGetSymbolAddress((void**)&aoh,  g_aoh);
    cudaGetSymbolAddress((void**)&aol,  g_aol);

    static bool attr_set = false;
    if (!attr_set) {
        cudaFuncSetAttribute(gemm_mma, cudaFuncAttributeMaxDynamicSharedMemorySize,
                             GEMM_SMEM);
        cudaFuncSetAttribute(flash_attn_mma, cudaFuncAttributeMaxDynamicSharedMemorySize,
                             AT_SMEM);
        attr_set = true;
    }

    const int n4x = ROWS_ * DIM_ / 4;
    conv_split<<<(n4x + 255) / 256, 256>>>(x, xh, xl, n4x);
    conv_wt<<<dim3(INNER_ / 32, DIM_ / 32), dim3(32, 8)>>>(Wq,  INNER_,     wt, 0);
    conv_wt<<<dim3(2 * INNER_ / 32, DIM_ / 32), dim3(32, 8)>>>(Wkv, 2 * INNER_, wt, 1024);
    conv_wt<<<dim3(DIM_ / 32, INNER_ / 32), dim3(32, 8)>>>(Wo,  DIM_,       wot, 0);

    // fused QKV projection (2-pass fp16) -> split fp16 output
    gemm_mma<<<dim3(QKV_N / 128, ROWS_ / 128), 256, GEMM_SMEM>>>(
        xh, xl, wt, nullptr, nullptr, qkvh, qkvl, QKV_N, DIM_);

    // fp16 flash attention (2-pass) -> split fp16 output
    flash_attn_mma<<<dim3(N_ / 128, H_, B_), 256, AT_SMEM>>>(qkvh, qkvl, aoh, aol);

    // out = ao @ Wo + bo (2-pass fp16, fp32 output)
    gemm_mma<<<dim3(DIM_ / 128, ROWS_ / 128), 256, GEMM_SMEM>>>(
        aoh, aol, wot, bo, out, nullptr, nullptr, DIM_, INNER_);
}

// round 9
// speedup vs baseline: 5.4085x; 1.2996x over previous
#include <cuda_runtime.h>
#include <cuda_bf16.h>
#include <cuda_fp16.h>
#include <math.h>
#include <cstdint>

// Problem constants
#define B_    4
#define N_    2048
#define DIM_  1024
#define H_    16
#define DH_   64
#define INNER_ 1024
#define ROWS_ (B_ * N_)   // 8192
#define QKV_N 3072        // fused [Q|K|V] columns

// ---------------------------------------------------------------------------
// Scratch (device globals — no cudaMalloc allowed)
// ---------------------------------------------------------------------------
__device__ __half g_qkvh[ROWS_ * QKV_N], g_qkvl[ROWS_ * QKV_N];
__device__ __half g_xh[ROWS_ * DIM_];           // x as single fp16
__device__ __half g_wt [QKV_N * DIM_];          // [n][k] fp16 single
__device__ __half g_wot[DIM_ * INNER_];         // [n][k] fp16 single
__device__ __half g_aoh[ROWS_ * INNER_];        // attention out, single fp16

// ---------------------------------------------------------------------------
// helpers
// ---------------------------------------------------------------------------
__device__ __forceinline__ uint32_t smem_u32(const void* p) {
    uint32_t a;
    asm("{ .reg .u64 t; cvta.to.shared.u64 t, %1; cvt.u32.u64 %0, t; }"
        : "=r"(a) : "l"(p));
    return a;
}
#define CP16(dst, src) \
    asm volatile("cp.async.cg.shared.global [%0], [%1], 16;" :: "r"(dst), "l"(src))

__device__ __forceinline__ void ldsm_x4(uint32_t* r, uint32_t addr) {
    asm volatile("ldmatrix.sync.aligned.m8n8.x4.shared.b16 {%0,%1,%2,%3}, [%4];"
                 : "=r"(r[0]), "=r"(r[1]), "=r"(r[2]), "=r"(r[3]) : "r"(addr));
}
__device__ __forceinline__ void ldsm_x4t(uint32_t* r, uint32_t addr) {
    asm volatile("ldmatrix.sync.aligned.m8n8.x4.trans.shared.b16 {%0,%1,%2,%3}, [%4];"
                 : "=r"(r[0]), "=r"(r[1]), "=r"(r[2]), "=r"(r[3]) : "r"(addr));
}
__device__ __forceinline__ void mma_fp16(float* d, const uint32_t* a, const uint32_t* b) {
    asm volatile(
        "mma.sync.aligned.m16n8k16.row.col.f32.f16.f16.f32 "
        "{%0,%1,%2,%3}, {%4,%5,%6,%7}, {%8,%9}, {%0,%1,%2,%3};"
        : "+f"(d[0]), "+f"(d[1]), "+f"(d[2]), "+f"(d[3])
        : "r"(a[0]), "r"(a[1]), "r"(a[2]), "r"(a[3]), "r"(b[0]), "r"(b[1]));
}
// fp16 pack helpers
__device__ __forceinline__ uint32_t packhf(float lo, float hi) {
    __half2 t = __floats2half2_rn(lo, hi);
    return *reinterpret_cast<uint32_t*>(&t);
}
__device__ __forceinline__ float hflo_f(uint32_t p) {
    return __half2float(__ushort_as_half((unsigned short)(p & 0xffffu)));
}
__device__ __forceinline__ float hfhi_f(uint32_t p) {
    return __half2float(__ushort_as_half((unsigned short)(p >> 16)));
}

// ---------------------------------------------------------------------------
// fp32 -> fp16 element-wise convert
// ---------------------------------------------------------------------------
__global__ void conv_half(const float* __restrict__ in,
                          __half* __restrict__ hi, int n4)
{
    int i = blockIdx.x * blockDim.x + threadIdx.x;
    if (i >= n4) return;
    float4 v = ((const float4*)in)[i];
    __half2* H = (__half2*)hi;
    H[i * 2]     = __floats2half2_rn(v.x, v.y);
    H[i * 2 + 1] = __floats2half2_rn(v.z, v.w);
}

// ---------------------------------------------------------------------------
// W[k][n] fp32 -> Wt[n][k] fp16 single, rows [row_off, row_off+Nw), ld=1024
// ---------------------------------------------------------------------------
__global__ void conv_wt(const float* __restrict__ W, int Nw,
                        __half* __restrict__ outh, int row_off)
{
    __shared__ float t[32][33];
    const int bn = blockIdx.x * 32, bk = blockIdx.y * 32;
    const int tx = threadIdx.x, ty = threadIdx.y;
#pragma unroll
    for (int i = 0; i < 4; i++)
        t[ty + i * 8][tx] = W[(size_t)(bk + ty + i * 8) * Nw + bn + tx];
    __syncthreads();
#pragma unroll
    for (int i = 0; i < 4; i++) {
        float v = t[tx][ty + i * 8];
        size_t o = (size_t)(row_off + bn + ty + i * 8) * 1024 + bk + tx;
        outh[o] = __float2half_rn(v);
    }
}

// ---------------------------------------------------------------------------
// Single-pass fp16 GEMM: C[M,N] = A[M,1024] * B[N,1024]^T (+bias)
// A, B single fp16 ([n][k] B, non-trans ldmatrix). Tile 128x128x64,
// 4-stage cp.async pipeline. If Ch != null: write split fp16 hi/lo.
// ---------------------------------------------------------------------------
#define BKg   64
#define LDS_  72                      // BK + 8 pad (halves); 144 B/row
#define TILE_B (128 * LDS_ * 2)       // 18432 B per matrix tile
#define STAGE_B (2 * TILE_B)          // A, B = 36864
#define NSTG  4
#define GEMM_SMEM (NSTG * STAGE_B)    // 147456 B

__global__ __launch_bounds__(256, 1)
void gemm_mma(const __half* __restrict__ Am, const __half* __restrict__ Bm,
              const float* __restrict__ bias, float* __restrict__ C,
              __half* __restrict__ Ch, __half* __restrict__ Cl,
              int ldC, int Kd)
{
    extern __shared__ char sm[];
    const uint32_t smb = smem_u32(sm);
    const int tid = threadIdx.x, wid = tid >> 5, lane = tid & 31;
    const int m0 = blockIdx.y * 128, n0 = blockIdx.x * 128;
    const int warp_m = (wid >> 2) * 64;    // 0 or 64
    const int warp_n = (wid & 3) * 32;     // 0,32,64,96

    float acc[4][4][4];
#pragma unroll
    for (int a = 0; a < 4; a++)
#pragma unroll
        for (int b = 0; b < 4; b++)
#pragma unroll
            for (int c = 0; c < 4; c++) acc[a][b][c] = 0.f;

    const int n_iters = Kd / BKg;

    auto issue_stage = [&](int buf, int k0) {
        const uint32_t sb = smb + buf * STAGE_B;
#pragma unroll
        for (int p = 0; p < 4; ++p) {
            const int idx = tid + p * 256;       // 0..1023
            const int r = idx >> 3;              // 0..127
            const int c = idx & 7;               // 0..7 (16B chunks)
            const uint32_t so = (uint32_t)r * (LDS_ * 2) + c * 16;
            const size_t goA = (size_t)(m0 + r) * 1024 + k0 + c * 8;
            const size_t goB = (size_t)(n0 + r) * 1024 + k0 + c * 8;
            CP16(sb + so,          (const char*)(Am + goA));
            CP16(sb + TILE_B + so, (const char*)(Bm + goB));
        }
        asm volatile("cp.async.commit_group;" ::: "memory");
    };

    issue_stage(0, 0);
    issue_stage(1, BKg);
    issue_stage(2, 2 * BKg);

    const int a_row = warp_m + (lane & 15);
    const int a_col = (lane >> 4) << 3;
    const int b_row = warp_n + (lane & 7) + ((lane & 16) >> 1);
    const int b_col = (lane & 8);

    for (int it = 0; it < n_iters; ++it) {
        asm volatile("cp.async.wait_group 2;" ::: "memory");
        __syncthreads();
        if (it + 3 < n_iters) issue_stage((it + 3) % NSTG, (it + 3) * BKg);

        const uint32_t sb = smb + (it % NSTG) * STAGE_B;
        const uint32_t sA = sb, sB = sb + TILE_B;

#pragma unroll
        for (int ks = 0; ks < BKg / 16; ++ks) {
            const int koff = ks * 16;
            uint32_t af[4][4];
            uint32_t bf[4][2];
#pragma unroll
            for (int mf = 0; mf < 4; ++mf) {
                const uint32_t ao =
                    (uint32_t)(a_row + mf * 16) * (LDS_ * 2) + (a_col + koff) * 2;
                ldsm_x4(af[mf], sA + ao);
            }
#pragma unroll
            for (int g = 0; g < 2; ++g) {
                const uint32_t bo =
                    (uint32_t)(b_row + g * 16) * (LDS_ * 2) + (b_col + koff) * 2;
                uint32_t th[4];
                ldsm_x4(th, sB + bo);        // NON-trans: B stored [n][k]
                bf[g * 2][0] = th[0]; bf[g * 2][1] = th[1];
                bf[g * 2 + 1][0] = th[2]; bf[g * 2 + 1][1] = th[3];
            }
#pragma unroll
            for (int mf = 0; mf < 4; ++mf)
#pragma unroll
                for (int nf = 0; nf < 4; ++nf)
                    mma_fp16(acc[mf][nf], af[mf], bf[nf]);
        }
    }

    // ---- epilogue ----
    const int gid = lane >> 2, tig = lane & 3;
#pragma unroll
    for (int mf = 0; mf < 4; ++mf)
#pragma unroll
        for (int nf = 0; nf < 4; ++nf) {
            const int col = n0 + warp_n + nf * 8 + tig * 2;
            const int row0 = m0 + warp_m + mf * 16 + gid;
            if (Ch) {
                // split fp16 output (attention Q path needs hi+lo)
#pragma unroll
                for (int rr = 0; rr < 2; ++rr) {
                    const float e0 = acc[mf][nf][rr * 2], e1 = acc[mf][nf][rr * 2 + 1];
                    const uint32_t hp = packhf(e0, e1);
                    const uint32_t lp = packhf(e0 - hflo_f(hp), e1 - hfhi_f(hp));
                    const size_t off = (size_t)(row0 + rr * 8) * ldC + col;
                    *(uint32_t*)(Ch + off) = hp;
                    *(uint32_t*)(Cl + off) = lp;
                }
            } else {
                float2 v0 = make_float2(acc[mf][nf][0], acc[mf][nf][1]);
                float2 v1 = make_float2(acc[mf][nf][2], acc[mf][nf][3]);
                if (bias) {
                    const float b0 = bias[col], b1 = bias[col + 1];
                    v0.x += b0; v0.y += b1; v1.x += b0; v1.y += b1;
                }
                *(float2*)(C + (size_t)row0 * ldC + col) = v0;
                *(float2*)(C + (size_t)(row0 + 8) * ldC + col) = v1;
            }
        }
}

// ---------------------------------------------------------------------------
// Flash attention (causal), fp16 tensor cores:
//   QK^T = (Qh+Ql) * Kh (2-pass) ;  PV = (Ph+Pl) * Vh (2-pass)
// CTA = 128 q rows of one (b,h); 8 warps x 16 rows. Key tiles of 64.
// 3-stage KV pipeline, reversed ib for causal balance. Output: single fp16.
// ---------------------------------------------------------------------------
#define AST   72                       // smem row stride in halves
#define QT_B  (128 * AST * 2)          // 18432
#define KT_B  (64 * AST * 2)           // 9216
#define KV_STAGE (2 * KT_B)            // 18432 (Kh, Vh)
#define AT_SMEM (2 * QT_B + 3 * KV_STAGE)   // 92160

__global__ __launch_bounds__(256, 1)
void flash_attn_mma(const __half* __restrict__ qkvh,
                    const __half* __restrict__ qkvl,
                    __half* __restrict__ aoh)
{
    extern __shared__ char sm[];
    const uint32_t smb = smem_u32(sm);
    const uint32_t sQh = smb, sQl = smb + QT_B;
    const uint32_t kvb = smb + 2 * QT_B;

    const int tid = threadIdx.x, wid = tid >> 5, lane = tid & 31;
    const int gid = lane >> 2, tig = lane & 3;
    const int b = blockIdx.z, h = blockIdx.y;
    const int ib = gridDim.x - 1 - blockIdx.x;   // longest CTAs scheduled first

    const size_t rowQ0 = (size_t)b * N_ + ib * 128;
    const int colQ = h * DH_;
    const int colK = INNER_ + h * DH_;
    const int colV = 2 * INNER_ + h * DH_;

    // ---- Q loads (hi+lo), committed with first KV group ----
#pragma unroll
    for (int p = 0; p < 4; ++p) {
        const int idx = tid + p * 256;      // 0..1023
        const int r = idx >> 3, c = idx & 7;
        const uint32_t so = (uint32_t)r * (AST * 2) + c * 16;
        const size_t go = (rowQ0 + r) * QKV_N + colQ + c * 8;
        CP16(sQh + so, (const char*)(qkvh + go));
        CP16(sQl + so, (const char*)(qkvl + go));
    }

    auto issue_kv = [&](int jb, int buf) {
        const uint32_t sb = kvb + buf * KV_STAGE;
        const size_t rowK0 = (size_t)b * N_ + jb * 64;
#pragma unroll
        for (int p = 0; p < 2; ++p) {
            const int idx = tid + p * 256;  // 0..511
            const int r = idx >> 3, c = idx & 7;
            const uint32_t so = (uint32_t)r * (AST * 2) + c * 16;
            const size_t gk = (rowK0 + r) * QKV_N + colK + c * 8;
            const size_t gv = (rowK0 + r) * QKV_N + colV + c * 8;
            CP16(sb + so,        (const char*)(qkvh + gk));   // Kh
            CP16(sb + KT_B + so, (const char*)(qkvh + gv));   // Vh
        }
        asm volatile("cp.async.commit_group;" ::: "memory");
    };

    issue_kv(0, 0);
    issue_kv(1, 1);

    float o[8][4];
#pragma unroll
    for (int i = 0; i < 8; i++)
#pragma unroll
        for (int j = 0; j < 4; j++) o[i][j] = 0.f;
    float m0 = -INFINITY, m1 = -INFINITY, l0 = 0.f, l1 = 0.f;

    // fragment addressing
    const int a_row = wid * 16 + (lane & 15);
    const int a_col = (lane >> 4) << 3;
    const int bk_row = (lane & 7) + ((lane & 16) >> 1);   // K b-frag (non-trans)
    const int bk_col = (lane & 8);
    const int v_row = (lane & 15);                        // V b-frag (trans)
    const int v_col = (lane >> 4) << 3;

    const int row0g = ib * 128 + wid * 16 + gid;          // global q rows
    const int row1g = row0g + 8;
    const int ntiles = 2 * ib + 2;

    for (int jb = 0; jb < ntiles; ++jb) {
        asm volatile("cp.async.wait_group 1;" ::: "memory");
        __syncthreads();
        if (jb + 2 < ntiles) issue_kv(jb + 2, (jb + 2) % 3);

        const uint32_t sb = kvb + (jb % 3) * KV_STAGE;
        const uint32_t sKh = sb, sVh = sb + KT_B;

        // ---- S = Q K^T (2 passes: Qh*K + Ql*K) ----
        float s[8][4];
#pragma unroll
        for (int i = 0; i < 8; i++)
#pragma unroll
            for (int j = 0; j < 4; j++) s[i][j] = 0.f;

#pragma unroll
        for (int ks = 0; ks < 4; ++ks) {
            uint32_t qh[4], ql[4];
            const uint32_t ao = (uint32_t)a_row * (AST * 2) + (a_col + ks * 16) * 2;
            ldsm_x4(qh, sQh + ao);
            ldsm_x4(ql, sQl + ao);
#pragma unroll
            for (int g = 0; g < 4; ++g) {
                const uint32_t bo =
                    (uint32_t)(g * 16 + bk_row) * (AST * 2) + (ks * 16 + bk_col) * 2;
                uint32_t kh[4];
                ldsm_x4(kh, sKh + bo);
                mma_fp16(s[g * 2],     qh, kh);
                mma_fp16(s[g * 2],     ql, kh);
                mma_fp16(s[g * 2 + 1], qh, kh + 2);
                mma_fp16(s[g * 2 + 1], ql, kh + 2);
            }
        }

        // ---- scale + causal mask ----
#pragma unroll
        for (int nf = 0; nf < 8; ++nf)
#pragma unroll
            for (int e = 0; e < 4; ++e) s[nf][e] *= 0.125f;
        if (jb >= 2 * ib) {
#pragma unroll
            for (int nf = 0; nf < 8; ++nf) {
                const int col = jb * 64 + nf * 8 + tig * 2;
                if (col     > row0g) s[nf][0] = -INFINITY;
                if (col + 1 > row0g) s[nf][1] = -INFINITY;
                if (col     > row1g) s[nf][2] = -INFINITY;
                if (col + 1 > row1g) s[nf][3] = -INFINITY;
            }
        }

        // ---- online softmax ----
        float mx0 = -INFINITY, mx1 = -INFINITY;
#pragma unroll
        for (int nf = 0; nf < 8; ++nf) {
            mx0 = fmaxf(mx0, fmaxf(s[nf][0], s[nf][1]));
            mx1 = fmaxf(mx1, fmaxf(s[nf][2], s[nf][3]));
        }
        mx0 = fmaxf(mx0, __shfl_xor_sync(0xffffffffu, mx0, 1));
        mx0 = fmaxf(mx0, __shfl_xor_sync(0xffffffffu, mx0, 2));
        mx1 = fmaxf(mx1, __shfl_xor_sync(0xffffffffu, mx1, 1));
        mx1 = fmaxf(mx1, __shfl_xor_sync(0xffffffffu, mx1, 2));
        const float nm0 = fmaxf(m0, mx0), nm1 = fmaxf(m1, mx1);
        const float fac0 = __expf(m0 - nm0), fac1 = __expf(m1 - nm1);
        m0 = nm0; m1 = nm1;

        float sum0 = 0.f, sum1 = 0.f;
#pragma unroll
        for (int nf = 0; nf < 8; ++nf) {
            s[nf][0] = __expf(s[nf][0] - nm0);
            s[nf][1] = __expf(s[nf][1] - nm0);
            s[nf][2] = __expf(s[nf][2] - nm1);
            s[nf][3] = __expf(s[nf][3] - nm1);
            sum0 += s[nf][0] + s[nf][1];
            sum1 += s[nf][2] + s[nf][3];
        }
        sum0 += __shfl_xor_sync(0xffffffffu, sum0, 1);
        sum0 += __shfl_xor_sync(0xffffffffu, sum0, 2);
        sum1 += __shfl_xor_sync(0xffffffffu, sum1, 1);
        sum1 += __shfl_xor_sync(0xffffffffu, sum1, 2);
        l0 = l0 * fac0 + sum0;
        l1 = l1 * fac1 + sum1;
#pragma unroll
        for (int nf = 0; nf < 8; ++nf) {
            o[nf][0] *= fac0; o[nf][1] *= fac0;
            o[nf][2] *= fac1; o[nf][3] *= fac1;
        }

        // ---- O += P V (2 passes: Ph*V + Pl*V); P repacked C->A frag fp16 ----
#pragma unroll
        for (int kb = 0; kb < 4; ++kb) {
            uint32_t ph[4], pl[4];
#pragma unroll
            for (int half = 0; half < 2; ++half) {
                const float* pp = s[2 * kb + half];
                const uint32_t h01 = packhf(pp[0], pp[1]);
                const uint32_t h23 = packhf(pp[2], pp[3]);
                const uint32_t l01 = packhf(pp[0] - hflo_f(h01), pp[1] - hfhi_f(h01));
                const uint32_t l23 = packhf(pp[2] - hflo_f(h23), pp[3] - hfhi_f(h23));
                ph[half * 2] = h01; ph[half * 2 + 1] = h23;
                pl[half * 2] = l01; pl[half * 2 + 1] = l23;
            }
#pragma unroll
            for (int g = 0; g < 4; ++g) {
                const uint32_t bo =
                    (uint32_t)(kb * 16 + v_row) * (AST * 2) + (g * 16 + v_col) * 2;
                uint32_t vh[4];
                ldsm_x4t(vh, sVh + bo);
                mma_fp16(o[g * 2],     ph, vh);
                mma_fp16(o[g * 2],     pl, vh);
                mma_fp16(o[g * 2 + 1], ph, vh + 2);
                mma_fp16(o[g * 2 + 1], pl, vh + 2);
            }
        }
    }

    // ---- epilogue: normalize, single fp16 store ----
    const float inv0 = 1.f / l0, inv1 = 1.f / l1;
    const size_t gr0 = (size_t)b * N_ + ib * 128 + wid * 16 + gid;
#pragma unroll
    for (int nf = 0; nf < 8; ++nf) {
        const int col = h * DH_ + nf * 8 + tig * 2;
        *(uint32_t*)(aoh + gr0 * INNER_ + col) =
            packhf(o[nf][0] * inv0, o[nf][1] * inv0);
        *(uint32_t*)(aoh + (gr0 + 8) * INNER_ + col) =
            packhf(o[nf][2] * inv1, o[nf][3] * inv1);
    }
}

// ---------------------------------------------------------------------------
extern "C" void kernel_launch(void* const* d_in, const int* in_sizes, int n_in,
                              void* d_out, int out_size)
{
    const float* x   = (const float*)d_in[0];
    const float* Wq  = (const float*)d_in[1];
    const float* Wkv = (const float*)d_in[2];
    const float* Wo  = (const float*)d_in[3];
    const float* bo  = (const float*)d_in[4];
    float* out = (float*)d_out;

    __half *qkvh, *qkvl, *xh, *wt, *wot, *aoh;
    cudaGetSymbolAddress((void**)&qkvh, g_qkvh);
    cudaGetSymbolAddress((void**)&qkvl, g_qkvl);
    cudaGetSymbolAddress((void**)&xh,   g_xh);
    cudaGetSymbolAddress((void**)&wt,   g_wt);
    cudaGetSymbolAddress((void**)&wot,  g_wot);
    cudaGetSymbolAddress((void**)&aoh,  g_aoh);

    static bool attr_set = false;
    if (!attr_set) {
        cudaFuncSetAttribute(gemm_mma, cudaFuncAttributeMaxDynamicSharedMemorySize,
                             GEMM_SMEM);
        cudaFuncSetAttribute(flash_attn_mma, cudaFuncAttributeMaxDynamicSharedMemorySize,
                             AT_SMEM);
        attr_set = true;
    }

    const int n4x = ROWS_ * DIM_ / 4;
    conv_half<<<(n4x + 255) / 256, 256>>>(x, xh, n4x);
    conv_wt<<<dim3(INNER_ / 32, DIM_ / 32), dim3(32, 8)>>>(Wq,  INNER_,     wt, 0);
    conv_wt<<<dim3(2 * INNER_ / 32, DIM_ / 32), dim3(32, 8)>>>(Wkv, 2 * INNER_, wt, 1024);
    conv_wt<<<dim3(DIM_ / 32, INNER_ / 32), dim3(32, 8)>>>(Wo,  DIM_,       wot, 0);

    // fused QKV projection (1-pass fp16) -> split fp16 output (hi+lo)
    gemm_mma<<<dim3(QKV_N / 128, ROWS_ / 128), 256, GEMM_SMEM>>>(
        xh, wt, nullptr, nullptr, qkvh, qkvl, QKV_N, DIM_);

    // fp16 flash attention -> single fp16 output
    flash_attn_mma<<<dim3(N_ / 128, H_, B_), 256, AT_SMEM>>>(qkvh, qkvl, aoh);

    // out = ao @ Wo + bo (1-pass fp16, fp32 output)
    gemm_mma<<<dim3(DIM_ / 128, ROWS_ / 128), 256, GEMM_SMEM>>>(
        aoh, wot, bo, out, nullptr, nullptr, DIM_, INNER_);
}